// round 1
// baseline (speedup 1.0000x reference)
#include <cuda_runtime.h>
#include <math.h>

// ---------------- problem constants ----------------
#define LAYERS 6
#define BATCH  2
#define SEQ    1024
#define DMODEL 1024
#define NHEAD  16
#define HDIM   64
#define DFF    4096
#define WIN    5
#define TOKENS (BATCH*SEQ)          // 2048
#define EPS    1e-5f

// ---------------- device scratch (no allocation allowed) ----------------
__device__ float d_h   [TOKENS*DMODEL];            // residual stream  (8 MB)
__device__ float d_hn  [TOKENS*DMODEL];            // LN output        (8 MB)
__device__ float d_qkv [TOKENS*3*DMODEL];          // qkv              (24 MB)
__device__ float d_o   [TOKENS*DMODEL];            // attn out         (8 MB)
__device__ float d_ff  [TOKENS*DFF];               // ffn mid          (32 MB)
__device__ float d_sc  [(size_t)BATCH*NHEAD*SEQ*SEQ]; // scores/probs  (134 MB)

// ---------------- helpers ----------------
__device__ __forceinline__ float warp_sum(float v){
    #pragma unroll
    for (int o = 16; o; o >>= 1) v += __shfl_xor_sync(0xffffffffu, v, o);
    return v;
}
__device__ __forceinline__ float warp_max(float v){
    #pragma unroll
    for (int o = 16; o; o >>= 1) v = fmaxf(v, __shfl_xor_sync(0xffffffffu, v, o));
    return v;
}
__device__ __forceinline__ float gelu_exact(float x){
    return 0.5f * x * (1.0f + erff(x * 0.70710678118654752440f));
}

// ---------------- copy x -> h ----------------
__global__ void copy_kernel(const float* __restrict__ in, float* __restrict__ out){
    int idx = blockIdx.x * blockDim.x + threadIdx.x;     // float4 index
    float4 v = ((const float4*)in)[idx];
    ((float4*)out)[idx] = v;
}

// ---------------- LayerNorm: one block per row of 1024 ----------------
__global__ void ln_kernel(const float* __restrict__ in,
                          const float* __restrict__ w,
                          const float* __restrict__ b,
                          float* __restrict__ out){
    int row = blockIdx.x;
    int t   = threadIdx.x;                                // 256 threads
    const float* x = in + (size_t)row * DMODEL;
    float4 v = *(const float4*)&x[t*4];
    float s  = v.x + v.y + v.z + v.w;
    float sq = v.x*v.x + v.y*v.y + v.z*v.z + v.w*v.w;
    s  = warp_sum(s);
    sq = warp_sum(sq);
    __shared__ float sh1[8], sh2[8];
    int warp = t >> 5, lane = t & 31;
    if (lane == 0){ sh1[warp] = s; sh2[warp] = sq; }
    __syncthreads();
    float tot = 0.f, tot2 = 0.f;
    #pragma unroll
    for (int i = 0; i < 8; i++){ tot += sh1[i]; tot2 += sh2[i]; }
    float mu   = tot  * (1.0f/DMODEL);
    float var  = tot2 * (1.0f/DMODEL) - mu*mu;
    float rstd = rsqrtf(var + EPS);
    float4 wv = *(const float4*)&w[t*4];
    float4 bv = *(const float4*)&b[t*4];
    float4 ov;
    ov.x = (v.x - mu)*rstd*wv.x + bv.x;
    ov.y = (v.y - mu)*rstd*wv.y + bv.y;
    ov.z = (v.z - mu)*rstd*wv.z + bv.z;
    ov.w = (v.w - mu)*rstd*wv.w + bv.w;
    *(float4*)&out[(size_t)row*DMODEL + t*4] = ov;
}

// ---------------- tiled SGEMM 128x128x8, 256 threads, 8x8/thread ----------------
// C[M,N] = epi( A[M,K] @ B[K,N] + bias[N] (+ res[M,N]) )
// EPI: 0 = bias   1 = bias + residual   2 = bias + exact GELU
template<int EPI>
__global__ __launch_bounds__(256)
void gemm_kernel(const float* __restrict__ A, const float* __restrict__ B,
                 const float* __restrict__ bias, const float* __restrict__ res,
                 float* __restrict__ C, int M, int N, int K){
    __shared__ float As[8][128];   // As[k][m]
    __shared__ float Bs[8][128];   // Bs[k][n]
    int t  = threadIdx.x;
    int m0 = blockIdx.y * 128, n0 = blockIdx.x * 128;
    int a_row = t >> 1,  a_col = (t & 1) * 4;     // A: 128 rows x 8 k
    int b_row = t >> 5,  b_col = (t & 31) * 4;    // B: 8 k x 128 cols
    int tx = t & 15, ty = t >> 4;

    float acc[8][8];
    #pragma unroll
    for (int i = 0; i < 8; i++)
        #pragma unroll
        for (int j = 0; j < 8; j++) acc[i][j] = 0.f;

    const float* Ap = A + (size_t)(m0 + a_row) * K + a_col;
    const float* Bp = B + (size_t)b_row * N + n0 + b_col;

    for (int k0 = 0; k0 < K; k0 += 8){
        float4 av = *(const float4*)(Ap + k0);
        float4 bv = *(const float4*)(Bp + (size_t)k0 * N);
        __syncthreads();
        As[a_col+0][a_row] = av.x;
        As[a_col+1][a_row] = av.y;
        As[a_col+2][a_row] = av.z;
        As[a_col+3][a_row] = av.w;
        *(float4*)&Bs[b_row][b_col] = bv;
        __syncthreads();
        #pragma unroll
        for (int kk = 0; kk < 8; kk++){
            float a[8], bb[8];
            float4 a0 = *(const float4*)&As[kk][ty*8];
            float4 a1 = *(const float4*)&As[kk][ty*8+4];
            float4 b0 = *(const float4*)&Bs[kk][tx*8];
            float4 b1 = *(const float4*)&Bs[kk][tx*8+4];
            a[0]=a0.x; a[1]=a0.y; a[2]=a0.z; a[3]=a0.w;
            a[4]=a1.x; a[5]=a1.y; a[6]=a1.z; a[7]=a1.w;
            bb[0]=b0.x; bb[1]=b0.y; bb[2]=b0.z; bb[3]=b0.w;
            bb[4]=b1.x; bb[5]=b1.y; bb[6]=b1.z; bb[7]=b1.w;
            #pragma unroll
            for (int i = 0; i < 8; i++)
                #pragma unroll
                for (int j = 0; j < 8; j++)
                    acc[i][j] = fmaf(a[i], bb[j], acc[i][j]);
        }
    }
    #pragma unroll
    for (int i = 0; i < 8; i++){
        int m = m0 + ty*8 + i;
        #pragma unroll
        for (int j = 0; j < 8; j++){
            int n = n0 + tx*8 + j;
            float v = acc[i][j] + bias[n];
            if (EPI == 1) v += res[(size_t)m * N + n];
            if (EPI == 2) v = gelu_exact(v);
            C[(size_t)m * N + n] = v;
        }
    }
}

// ---------------- attention: scores = scale * Q K^T, causal mask ----------------
__global__ __launch_bounds__(256)
void scores_kernel(const float* __restrict__ qkv, float* __restrict__ sc){
    int bh = blockIdx.x;             // 0..31
    int it = blockIdx.y;             // q tile (64 rows)
    int jt = blockIdx.z;             // k tile (64 rows)
    if (jt > it) return;
    int b = bh >> 4, h = bh & 15;
    __shared__ float Qs[64][65];
    __shared__ float Ks[64][65];
    int t = threadIdx.x;
    const size_t base = (size_t)b * SEQ * 3 * DMODEL;
    #pragma unroll
    for (int p = 0; p < 4; p++){
        int idx = t + p*256;         // 0..1023 float4 slots (64 rows x 16)
        int r = idx >> 4;
        int c = (idx & 15) * 4;
        float4 qv = *(const float4*)&qkv[base + (size_t)(it*64 + r)*3*DMODEL + h*HDIM + c];
        float4 kv = *(const float4*)&qkv[base + (size_t)(jt*64 + r)*3*DMODEL + DMODEL + h*HDIM + c];
        Qs[r][c]=qv.x; Qs[r][c+1]=qv.y; Qs[r][c+2]=qv.z; Qs[r][c+3]=qv.w;
        Ks[r][c]=kv.x; Ks[r][c+1]=kv.y; Ks[r][c+2]=kv.z; Ks[r][c+3]=kv.w;
    }
    __syncthreads();
    int tx = t & 15, ty = t >> 4;
    float acc[4][4];
    #pragma unroll
    for (int i=0;i<4;i++)
        #pragma unroll
        for (int j=0;j<4;j++) acc[i][j]=0.f;
    #pragma unroll 8
    for (int d = 0; d < 64; d++){
        float a[4], bb[4];
        #pragma unroll
        for (int i=0;i<4;i++) a[i]  = Qs[ty*4+i][d];
        #pragma unroll
        for (int j=0;j<4;j++) bb[j] = Ks[tx*4+j][d];
        #pragma unroll
        for (int i=0;i<4;i++)
            #pragma unroll
            for (int j=0;j<4;j++) acc[i][j] = fmaf(a[i], bb[j], acc[i][j]);
    }
    const float scale = 0.125f;   // 1/sqrt(64)
    #pragma unroll
    for (int i=0;i<4;i++){
        int ig = it*64 + ty*4 + i;
        #pragma unroll
        for (int j=0;j<4;j++){
            int jg = jt*64 + tx*4 + j;
            float v = (jg <= ig) ? acc[i][j]*scale : -INFINITY;
            sc[((size_t)bh*SEQ + ig)*SEQ + jg] = v;
        }
    }
}

// ---------------- softmax over causal row; zeros above diagonal ----------------
__global__ __launch_bounds__(256)
void softmax_kernel(float* __restrict__ sc){
    int bh = blockIdx.x, i = blockIdx.y;
    float* row = sc + ((size_t)bh*SEQ + i)*SEQ;
    int n = i + 1;
    int t = threadIdx.x;
    float vals[4];
    float mx = -INFINITY;
    #pragma unroll
    for (int k = 0; k < 4; k++){
        int j = t + k*256;
        vals[k] = (j < n) ? row[j] : -INFINITY;
        mx = fmaxf(mx, vals[k]);
    }
    mx = warp_max(mx);
    __shared__ float sh[8];
    int warp = t >> 5, lane = t & 31;
    if (lane == 0) sh[warp] = mx;
    __syncthreads();
    float M = -INFINITY;
    #pragma unroll
    for (int w = 0; w < 8; w++) M = fmaxf(M, sh[w]);
    __syncthreads();
    float sum = 0.f;
    #pragma unroll
    for (int k = 0; k < 4; k++){
        float e = __expf(vals[k] - M);   // -inf -> 0
        vals[k] = e;
        sum += e;
    }
    sum = warp_sum(sum);
    if (lane == 0) sh[warp] = sum;
    __syncthreads();
    float S = 0.f;
    #pragma unroll
    for (int w = 0; w < 8; w++) S += sh[w];
    float inv = 1.0f / S;
    #pragma unroll
    for (int k = 0; k < 4; k++)
        row[t + k*256] = vals[k] * inv;   // j>i writes 0
}

// ---------------- PV: o = probs @ V (K-loop clipped at causal boundary) ----------------
__global__ __launch_bounds__(256)
void pv_kernel(const float* __restrict__ qkv, const float* __restrict__ sc,
               float* __restrict__ o){
    int bh = blockIdx.x, it = blockIdx.y;
    int b = bh >> 4, h = bh & 15;
    __shared__ float Ps[64][65];
    __shared__ float Vs[64][65];
    int t = threadIdx.x;
    int tx = t & 15, ty = t >> 4;
    float acc[4][4];
    #pragma unroll
    for (int i=0;i<4;i++)
        #pragma unroll
        for (int j=0;j<4;j++) acc[i][j]=0.f;
    const size_t vbase = (size_t)b * SEQ * 3 * DMODEL + 2*DMODEL + h*HDIM;
    int kmax = (it + 1) * 64;
    for (int k0 = 0; k0 < kmax; k0 += 64){
        #pragma unroll
        for (int p = 0; p < 4; p++){
            int idx = t + p*256;
            int r = idx >> 4;
            int c = (idx & 15) * 4;
            float4 pv = *(const float4*)&sc[((size_t)bh*SEQ + it*64 + r)*SEQ + k0 + c];
            float4 vv = *(const float4*)&qkv[vbase + (size_t)(k0 + r)*3*DMODEL + c];
            Ps[r][c]=pv.x; Ps[r][c+1]=pv.y; Ps[r][c+2]=pv.z; Ps[r][c+3]=pv.w;
            Vs[r][c]=vv.x; Vs[r][c+1]=vv.y; Vs[r][c+2]=vv.z; Vs[r][c+3]=vv.w;
        }
        __syncthreads();
        #pragma unroll 8
        for (int kk = 0; kk < 64; kk++){
            float a[4], bb[4];
            #pragma unroll
            for (int i=0;i<4;i++) a[i]  = Ps[ty*4+i][kk];
            #pragma unroll
            for (int j=0;j<4;j++) bb[j] = Vs[kk][tx*4+j];
            #pragma unroll
            for (int i=0;i<4;i++)
                #pragma unroll
                for (int j=0;j<4;j++) acc[i][j] = fmaf(a[i], bb[j], acc[i][j]);
        }
        __syncthreads();
    }
    #pragma unroll
    for (int i=0;i<4;i++){
        int s = it*64 + ty*4 + i;
        #pragma unroll
        for (int j=0;j<4;j++)
            o[((size_t)b*SEQ + s)*DMODEL + h*HDIM + tx*4 + j] = acc[i][j];
    }
}

// ---------------- final projection: one block per token, WIN=5 outputs ----------------
__global__ __launch_bounds__(256)
void pred_kernel(const float* __restrict__ hn, const float* __restrict__ Wp,
                 const float* __restrict__ bp, float* __restrict__ out){
    int row = blockIdx.x;
    int t = threadIdx.x;
    float local[WIN] = {0,0,0,0,0};
    const float* x = hn + (size_t)row * DMODEL;
    for (int k = t; k < DMODEL; k += 256){
        float xv = x[k];
        const float* wr = Wp + (size_t)k * WIN;
        #pragma unroll
        for (int w = 0; w < WIN; w++) local[w] = fmaf(xv, wr[w], local[w]);
    }
    __shared__ float red[WIN][256];
    #pragma unroll
    for (int w = 0; w < WIN; w++) red[w][t] = local[w];
    __syncthreads();
    for (int s = 128; s > 0; s >>= 1){
        if (t < s){
            #pragma unroll
            for (int w = 0; w < WIN; w++) red[w][t] += red[w][t + s];
        }
        __syncthreads();
    }
    if (t < WIN) out[(size_t)row * WIN + t] = red[t][0] + bp[t];
}

// ---------------- host orchestration ----------------
extern "C" void kernel_launch(void* const* d_in, const int* in_sizes, int n_in,
                              void* d_out, int out_size){
    const float* x     = (const float*)d_in[0];
    const float* Wqkv  = (const float*)d_in[1];
    const float* bqkv  = (const float*)d_in[2];
    const float* Wo    = (const float*)d_in[3];
    const float* bo    = (const float*)d_in[4];
    const float* ln1w  = (const float*)d_in[5];
    const float* ln1b  = (const float*)d_in[6];
    const float* W1    = (const float*)d_in[7];
    const float* b1    = (const float*)d_in[8];
    const float* W2    = (const float*)d_in[9];
    const float* b2    = (const float*)d_in[10];
    const float* ln2w  = (const float*)d_in[11];
    const float* ln2b  = (const float*)d_in[12];
    const float* lnfw  = (const float*)d_in[13];
    const float* lnfb  = (const float*)d_in[14];
    const float* Wp    = (const float*)d_in[15];
    const float* bp    = (const float*)d_in[16];
    float* out = (float*)d_out;

    float *g_h, *g_hn, *g_qkv, *g_o, *g_ff, *g_sc;
    cudaGetSymbolAddress((void**)&g_h,   d_h);
    cudaGetSymbolAddress((void**)&g_hn,  d_hn);
    cudaGetSymbolAddress((void**)&g_qkv, d_qkv);
    cudaGetSymbolAddress((void**)&g_o,   d_o);
    cudaGetSymbolAddress((void**)&g_ff,  d_ff);
    cudaGetSymbolAddress((void**)&g_sc,  d_sc);

    // h = x
    copy_kernel<<<TOKENS*DMODEL/4/256, 256>>>(x, g_h);

    for (int l = 0; l < LAYERS; l++){
        const float* wqkv = Wqkv + (size_t)l * DMODEL * 3*DMODEL;
        const float* bq   = bqkv + (size_t)l * 3*DMODEL;
        const float* wo   = Wo   + (size_t)l * DMODEL * DMODEL;
        const float* bO   = bo   + (size_t)l * DMODEL;
        const float* w1   = W1   + (size_t)l * DMODEL * DFF;
        const float* B1   = b1   + (size_t)l * DFF;
        const float* w2   = W2   + (size_t)l * DFF * DMODEL;
        const float* B2   = b2   + (size_t)l * DMODEL;

        // pre-norm attention
        ln_kernel<<<TOKENS, 256>>>(g_h, ln1w + l*DMODEL, ln1b + l*DMODEL, g_hn);
        gemm_kernel<0><<<dim3(3*DMODEL/128, TOKENS/128), 256>>>(
            g_hn, wqkv, bq, nullptr, g_qkv, TOKENS, 3*DMODEL, DMODEL);
        scores_kernel <<<dim3(BATCH*NHEAD, SEQ/64, SEQ/64), 256>>>(g_qkv, g_sc);
        softmax_kernel<<<dim3(BATCH*NHEAD, SEQ), 256>>>(g_sc);
        pv_kernel     <<<dim3(BATCH*NHEAD, SEQ/64), 256>>>(g_qkv, g_sc, g_o);
        // h += o @ Wo + bo   (residual fused in epilogue)
        gemm_kernel<1><<<dim3(DMODEL/128, TOKENS/128), 256>>>(
            g_o, wo, bO, g_h, g_h, TOKENS, DMODEL, DMODEL);

        // pre-norm FFN
        ln_kernel<<<TOKENS, 256>>>(g_h, ln2w + l*DMODEL, ln2b + l*DMODEL, g_hn);
        gemm_kernel<2><<<dim3(DFF/128, TOKENS/128), 256>>>(
            g_hn, w1, B1, nullptr, g_ff, TOKENS, DFF, DMODEL);
        gemm_kernel<1><<<dim3(DMODEL/128, TOKENS/128), 256>>>(
            g_ff, w2, B2, g_h, g_h, TOKENS, DMODEL, DFF);
    }

    // final LN + projection
    ln_kernel<<<TOKENS, 256>>>(g_h, lnfw, lnfb, g_hn);
    pred_kernel<<<TOKENS, 256>>>(g_hn, Wp, bp, out);
    (void)in_sizes; (void)n_in; (void)out_size;
}

// round 3
// speedup vs baseline: 2.2644x; 2.2644x over previous
#include <cuda_runtime.h>
#include <cuda_bf16.h>
#include <math.h>
#include <stdint.h>

// ---------------- problem constants ----------------
#define LAYERS 6
#define BATCH  2
#define SEQ    1024
#define DMODEL 1024
#define NHEAD  16
#define HDIM   64
#define DFF    4096
#define WIN    5
#define TOKENS (BATCH*SEQ)          // 2048
#define EPS    1e-5f

// weight scratch layout (elements)
#define QKV_ELEMS  (LAYERS*DMODEL*3*DMODEL)   // 18874368
#define WO_ELEMS   (LAYERS*DMODEL*DMODEL)     // 6291456
#define W1_ELEMS   (LAYERS*DMODEL*DFF)        // 25165824
#define W2_ELEMS   (LAYERS*DFF*DMODEL)        // 25165824
#define QKV_OFF 0
#define WO_OFF  (QKV_ELEMS)
#define W1_OFF  (WO_OFF + WO_ELEMS)
#define W2_OFF  (W1_OFF + W1_ELEMS)
#define WTOTAL  (W2_OFF + W2_ELEMS)           // 75497472

// ---------------- device scratch (no allocation allowed) ----------------
__device__ float d_h   [TOKENS*DMODEL];
__device__ float d_hn  [TOKENS*DMODEL];
__device__ __nv_bfloat16 d_hn_hi[TOKENS*DMODEL];
__device__ __nv_bfloat16 d_hn_lo[TOKENS*DMODEL];
__device__ float d_qkv [TOKENS*3*DMODEL];
__device__ __nv_bfloat16 d_o_hi[TOKENS*DMODEL];
__device__ __nv_bfloat16 d_o_lo[TOKENS*DMODEL];
__device__ __nv_bfloat16 d_ff_hi[TOKENS*DFF];
__device__ __nv_bfloat16 d_ff_lo[TOKENS*DFF];
__device__ float d_sc  [(size_t)BATCH*NHEAD*SEQ*SEQ];
__device__ __nv_bfloat16 d_w_hi[WTOTAL];
__device__ __nv_bfloat16 d_w_lo[WTOTAL];

// ---------------- small helpers ----------------
__device__ __forceinline__ float warp_sum(float v){
    #pragma unroll
    for (int o = 16; o; o >>= 1) v += __shfl_xor_sync(0xffffffffu, v, o);
    return v;
}
__device__ __forceinline__ float warp_max(float v){
    #pragma unroll
    for (int o = 16; o; o >>= 1) v = fmaxf(v, __shfl_xor_sync(0xffffffffu, v, o));
    return v;
}
__device__ __forceinline__ float gelu_exact(float x){
    return 0.5f * x * (1.0f + erff(x * 0.70710678118654752440f));
}
__device__ __forceinline__ uint32_t smem_u32(const void* p){
    uint32_t a;
    asm("{ .reg .u64 t; cvta.to.shared.u64 t, %1; cvt.u32.u64 %0, t; }" : "=r"(a) : "l"(p));
    return a;
}
// split fp32 -> bf16 hi (truncated) + bf16 lo (rounded remainder)
__device__ __forceinline__ void split_bf16(float x, uint16_t& hi, uint16_t& lo){
    uint32_t u  = __float_as_uint(x);
    uint32_t hu = u & 0xFFFF0000u;
    hi = (uint16_t)(hu >> 16);
    float l = x - __uint_as_float(hu);
    lo = __bfloat16_as_ushort(__float2bfloat16(l));
}

// ---------------- mma.sync / ldmatrix / cp.async wrappers ----------------
__device__ __forceinline__ void mma_bf16(float* d, const uint32_t* a, const uint32_t* b){
    asm volatile(
      "mma.sync.aligned.m16n8k16.row.col.f32.bf16.bf16.f32 "
      "{%0,%1,%2,%3}, {%4,%5,%6,%7}, {%8,%9}, {%0,%1,%2,%3};\n"
      : "+f"(d[0]), "+f"(d[1]), "+f"(d[2]), "+f"(d[3])
      : "r"(a[0]), "r"(a[1]), "r"(a[2]), "r"(a[3]), "r"(b[0]), "r"(b[1]));
}
__device__ __forceinline__ void ldsm_x4(uint32_t* r, uint32_t addr){
    asm volatile("ldmatrix.sync.aligned.m8n8.x4.shared.b16 {%0,%1,%2,%3}, [%4];"
      : "=r"(r[0]), "=r"(r[1]), "=r"(r[2]), "=r"(r[3]) : "r"(addr));
}
__device__ __forceinline__ void ldsm_x2t(uint32_t* r, uint32_t addr){
    asm volatile("ldmatrix.sync.aligned.m8n8.x2.trans.shared.b16 {%0,%1}, [%2];"
      : "=r"(r[0]), "=r"(r[1]) : "r"(addr));
}
__device__ __forceinline__ void cp16(uint32_t s, const void* g){
    asm volatile("cp.async.cg.shared.global [%0], [%1], 16;\n" :: "r"(s), "l"(g));
}

// ---------------- GEMM smem layout ----------------
// per stage: A_hi [128 rows x 32 k] stride 80B  (10240B)
//            A_lo                                (10240B)
//            B_hi [32 k x 128 n]  stride 272B   ( 8704B)
//            B_lo                                ( 8704B)
#define KC          32
#define A_STRIDE    80
#define B_STRIDE    272
#define A_LO_OFF    10240
#define B_OFF       20480
#define B_LO_OFF    8704
#define STAGE_BYTES 37888
#define GEMM_SMEM   (3*STAGE_BYTES)   // 113664

__device__ __forceinline__ void issue_stage(
    const __nv_bfloat16* __restrict__ Ah, const __nv_bfloat16* __restrict__ Al,
    const __nv_bfloat16* __restrict__ Bh, const __nv_bfloat16* __restrict__ Bl,
    uint32_t sb0, int tid, int m0, int n0, int K, int N, int c)
{
    uint32_t sb = sb0 + (uint32_t)(c % 3) * STAGE_BYTES;
    int k0 = c * KC;
    #pragma unroll
    for (int i = 0; i < 2; i++){
        int idx = tid + i*256;               // 512 chunks of 16B per matrix
        int r = idx >> 2, cc = idx & 3;      // row 0..127, 16B-chunk 0..3
        uint32_t sa = sb + r*A_STRIDE + cc*16;
        size_t g = (size_t)(m0 + r) * K + k0 + cc*8;
        cp16(sa,            Ah + g);
        cp16(sa + A_LO_OFF, Al + g);
    }
    #pragma unroll
    for (int i = 0; i < 2; i++){
        int idx = tid + i*256;
        int r = idx >> 4, cc = idx & 15;     // k-row 0..31, 16B-chunk 0..15
        uint32_t sa = sb + B_OFF + r*B_STRIDE + cc*16;
        size_t g = (size_t)(k0 + r) * N + n0 + cc*8;
        cp16(sa,            Bh + g);
        cp16(sa + B_LO_OFF, Bl + g);
    }
    asm volatile("cp.async.commit_group;");
}

// =====================================================================
// bf16x3 emulated-fp32 GEMM:  C[M,N] = epi(A @ B + bias)
// A,B pre-split into bf16 hi/lo (row-major). 128x128 tile, 256 thr.
// EPI: 0 = bias (f32 out)  1 = bias+residual (f32 out)
//      2 = bias+GELU, split bf16 hi/lo out
// =====================================================================
template<int EPI>
__global__ __launch_bounds__(256)
void gemm_bf16x3(const __nv_bfloat16* __restrict__ Ah, const __nv_bfloat16* __restrict__ Al,
                 const __nv_bfloat16* __restrict__ Bh, const __nv_bfloat16* __restrict__ Bl,
                 const float* __restrict__ bias, const float* __restrict__ res,
                 float* __restrict__ C,
                 __nv_bfloat16* __restrict__ Chi, __nv_bfloat16* __restrict__ Clo,
                 int M, int N, int K)
{
    extern __shared__ char smem[];
    const uint32_t sb0 = smem_u32(smem);
    const int tid  = threadIdx.x;
    const int lane = tid & 31, wid = tid >> 5;
    const int m0 = blockIdx.y * 128, n0 = blockIdx.x * 128;
    const int wm = (wid >> 2) * 64, wn = (wid & 3) * 32;

    float acc[4][4][4];
    #pragma unroll
    for (int a = 0; a < 4; a++)
        #pragma unroll
        for (int b = 0; b < 4; b++)
            #pragma unroll
            for (int cc = 0; cc < 4; cc++) acc[a][b][cc] = 0.f;

    const int nch = K / KC;
    issue_stage(Ah, Al, Bh, Bl, sb0, tid, m0, n0, K, N, 0);
    issue_stage(Ah, Al, Bh, Bl, sb0, tid, m0, n0, K, N, 1);

    const uint32_t a_lrow = wm + (lane & 15);
    const uint32_t a_lcol = (lane >> 4) * 8;
    const uint32_t b_lrow = (lane & 15);

    for (int c = 0; c < nch; c++){
        if (c + 2 < nch) issue_stage(Ah, Al, Bh, Bl, sb0, tid, m0, n0, K, N, c + 2);
        else asm volatile("cp.async.commit_group;");
        asm volatile("cp.async.wait_group %0;" :: "n"(2));
        __syncthreads();

        uint32_t sb = sb0 + (uint32_t)(c % 3) * STAGE_BYTES;
        #pragma unroll
        for (int ks = 0; ks < 2; ks++){
            uint32_t ah[4][4], al[4][4], bh[4][2], bl[4][2];
            #pragma unroll
            for (int mt = 0; mt < 4; mt++){
                uint32_t ad = sb + (a_lrow + mt*16)*A_STRIDE + (ks*16 + a_lcol)*2;
                ldsm_x4(ah[mt], ad);
                ldsm_x4(al[mt], ad + A_LO_OFF);
            }
            #pragma unroll
            for (int nt = 0; nt < 4; nt++){
                uint32_t bd = sb + B_OFF + (ks*16 + b_lrow)*B_STRIDE + (wn + nt*8)*2;
                ldsm_x2t(bh[nt], bd);
                ldsm_x2t(bl[nt], bd + B_LO_OFF);
            }
            #pragma unroll
            for (int mt = 0; mt < 4; mt++)
                #pragma unroll
                for (int nt = 0; nt < 4; nt++){
                    mma_bf16(acc[mt][nt], ah[mt], bh[nt]);
                    mma_bf16(acc[mt][nt], ah[mt], bl[nt]);
                    mma_bf16(acc[mt][nt], al[mt], bh[nt]);
                }
        }
        __syncthreads();
    }

    // ---- epilogue ----
    const int g  = lane >> 2;
    const int tq = (lane & 3) * 2;
    #pragma unroll
    for (int mt = 0; mt < 4; mt++){
        #pragma unroll
        for (int half = 0; half < 2; half++){
            int m = m0 + wm + mt*16 + g + half*8;
            #pragma unroll
            for (int nt = 0; nt < 4; nt++){
                int n = n0 + wn + nt*8 + tq;
                float v0 = acc[mt][nt][half*2+0] + bias[n];
                float v1 = acc[mt][nt][half*2+1] + bias[n+1];
                size_t gi = (size_t)m * N + n;
                if (EPI == 1){ v0 += res[gi]; v1 += res[gi+1]; }
                if (EPI == 2){
                    v0 = gelu_exact(v0); v1 = gelu_exact(v1);
                    uint16_t h0, l0, h1, l1;
                    split_bf16(v0, h0, l0);
                    split_bf16(v1, h1, l1);
                    *(uint32_t*)&Chi[gi] = (uint32_t)h0 | ((uint32_t)h1 << 16);
                    *(uint32_t*)&Clo[gi] = (uint32_t)l0 | ((uint32_t)l1 << 16);
                } else {
                    float2 o; o.x = v0; o.y = v1;
                    *(float2*)&C[gi] = o;
                }
            }
        }
    }
}

// ---------------- weight split: fp32 -> bf16 hi/lo ----------------
__global__ void wsplit_kernel(const float4* __restrict__ in,
                              uint2* __restrict__ hi, uint2* __restrict__ lo, int n4){
    int i = blockIdx.x * blockDim.x + threadIdx.x;
    if (i >= n4) return;
    float4 v = in[i];
    uint16_t h0,l0,h1,l1,h2,l2,h3,l3;
    split_bf16(v.x, h0, l0); split_bf16(v.y, h1, l1);
    split_bf16(v.z, h2, l2); split_bf16(v.w, h3, l3);
    uint2 H, L;
    H.x = (uint32_t)h0 | ((uint32_t)h1 << 16);
    H.y = (uint32_t)h2 | ((uint32_t)h3 << 16);
    L.x = (uint32_t)l0 | ((uint32_t)l1 << 16);
    L.y = (uint32_t)l2 | ((uint32_t)l3 << 16);
    hi[i] = H; lo[i] = L;
}

// ---------------- copy x -> h ----------------
__global__ void copy_kernel(const float* __restrict__ in, float* __restrict__ out){
    int idx = blockIdx.x * blockDim.x + threadIdx.x;
    float4 v = ((const float4*)in)[idx];
    ((float4*)out)[idx] = v;
}

// ---------------- LayerNorm (writes fp32 + bf16 hi/lo) ----------------
__global__ void ln_kernel(const float* __restrict__ in,
                          const float* __restrict__ w,
                          const float* __restrict__ b,
                          float* __restrict__ out,
                          __nv_bfloat16* __restrict__ out_hi,
                          __nv_bfloat16* __restrict__ out_lo){
    int row = blockIdx.x;
    int t   = threadIdx.x;                                // 256 threads
    const float* x = in + (size_t)row * DMODEL;
    float4 v = *(const float4*)&x[t*4];
    float s  = v.x + v.y + v.z + v.w;
    float sq = v.x*v.x + v.y*v.y + v.z*v.z + v.w*v.w;
    s  = warp_sum(s);
    sq = warp_sum(sq);
    __shared__ float sh1[8], sh2[8];
    int warp = t >> 5, lane = t & 31;
    if (lane == 0){ sh1[warp] = s; sh2[warp] = sq; }
    __syncthreads();
    float tot = 0.f, tot2 = 0.f;
    #pragma unroll
    for (int i = 0; i < 8; i++){ tot += sh1[i]; tot2 += sh2[i]; }
    float mu   = tot  * (1.0f/DMODEL);
    float var  = tot2 * (1.0f/DMODEL) - mu*mu;
    float rstd = rsqrtf(var + EPS);
    float4 wv = *(const float4*)&w[t*4];
    float4 bv = *(const float4*)&b[t*4];
    float4 ov;
    ov.x = (v.x - mu)*rstd*wv.x + bv.x;
    ov.y = (v.y - mu)*rstd*wv.y + bv.y;
    ov.z = (v.z - mu)*rstd*wv.z + bv.z;
    ov.w = (v.w - mu)*rstd*wv.w + bv.w;
    size_t base = (size_t)row*DMODEL + t*4;
    *(float4*)&out[base] = ov;
    uint16_t h0,l0,h1,l1,h2,l2,h3,l3;
    split_bf16(ov.x, h0, l0); split_bf16(ov.y, h1, l1);
    split_bf16(ov.z, h2, l2); split_bf16(ov.w, h3, l3);
    uint2 H, L;
    H.x = (uint32_t)h0 | ((uint32_t)h1 << 16);
    H.y = (uint32_t)h2 | ((uint32_t)h3 << 16);
    L.x = (uint32_t)l0 | ((uint32_t)l1 << 16);
    L.y = (uint32_t)l2 | ((uint32_t)l3 << 16);
    *(uint2*)&out_hi[base] = H;
    *(uint2*)&out_lo[base] = L;
}

// ---------------- attention: scores = scale * Q K^T, causal mask ----------------
__global__ __launch_bounds__(256)
void scores_kernel(const float* __restrict__ qkv, float* __restrict__ sc){
    int bh = blockIdx.x;
    int it = blockIdx.y;
    int jt = blockIdx.z;
    if (jt > it) return;
    int b = bh >> 4, h = bh & 15;
    __shared__ float Qs[64][65];
    __shared__ float Ks[64][65];
    int t = threadIdx.x;
    const size_t base = (size_t)b * SEQ * 3 * DMODEL;
    #pragma unroll
    for (int p = 0; p < 4; p++){
        int idx = t + p*256;
        int r = idx >> 4;
        int c = (idx & 15) * 4;
        float4 qv = *(const float4*)&qkv[base + (size_t)(it*64 + r)*3*DMODEL + h*HDIM + c];
        float4 kv = *(const float4*)&qkv[base + (size_t)(jt*64 + r)*3*DMODEL + DMODEL + h*HDIM + c];
        Qs[r][c]=qv.x; Qs[r][c+1]=qv.y; Qs[r][c+2]=qv.z; Qs[r][c+3]=qv.w;
        Ks[r][c]=kv.x; Ks[r][c+1]=kv.y; Ks[r][c+2]=kv.z; Ks[r][c+3]=kv.w;
    }
    __syncthreads();
    int tx = t & 15, ty = t >> 4;
    float acc[4][4];
    #pragma unroll
    for (int i=0;i<4;i++)
        #pragma unroll
        for (int j=0;j<4;j++) acc[i][j]=0.f;
    #pragma unroll 8
    for (int d = 0; d < 64; d++){
        float a[4], bb[4];
        #pragma unroll
        for (int i=0;i<4;i++) a[i]  = Qs[ty*4+i][d];
        #pragma unroll
        for (int j=0;j<4;j++) bb[j] = Ks[tx*4+j][d];
        #pragma unroll
        for (int i=0;i<4;i++)
            #pragma unroll
            for (int j=0;j<4;j++) acc[i][j] = fmaf(a[i], bb[j], acc[i][j]);
    }
    const float scale = 0.125f;
    #pragma unroll
    for (int i=0;i<4;i++){
        int ig = it*64 + ty*4 + i;
        #pragma unroll
        for (int j=0;j<4;j++){
            int jg = jt*64 + tx*4 + j;
            float v = (jg <= ig) ? acc[i][j]*scale : -INFINITY;
            sc[((size_t)bh*SEQ + ig)*SEQ + jg] = v;
        }
    }
}

// ---------------- softmax over causal row; zeros above diagonal ----------------
__global__ __launch_bounds__(256)
void softmax_kernel(float* __restrict__ sc){
    int bh = blockIdx.x, i = blockIdx.y;
    float* row = sc + ((size_t)bh*SEQ + i)*SEQ;
    int n = i + 1;
    int t = threadIdx.x;
    float vals[4];
    float mx = -INFINITY;
    #pragma unroll
    for (int k = 0; k < 4; k++){
        int j = t + k*256;
        vals[k] = (j < n) ? row[j] : -INFINITY;
        mx = fmaxf(mx, vals[k]);
    }
    mx = warp_max(mx);
    __shared__ float sh[8];
    int warp = t >> 5, lane = t & 31;
    if (lane == 0) sh[warp] = mx;
    __syncthreads();
    float M = -INFINITY;
    #pragma unroll
    for (int w = 0; w < 8; w++) M = fmaxf(M, sh[w]);
    __syncthreads();
    float sum = 0.f;
    #pragma unroll
    for (int k = 0; k < 4; k++){
        float e = __expf(vals[k] - M);
        vals[k] = e;
        sum += e;
    }
    sum = warp_sum(sum);
    if (lane == 0) sh[warp] = sum;
    __syncthreads();
    float S = 0.f;
    #pragma unroll
    for (int w = 0; w < 8; w++) S += sh[w];
    float inv = 1.0f / S;
    #pragma unroll
    for (int k = 0; k < 4; k++)
        row[t + k*256] = vals[k] * inv;
}

// ---------------- PV: o = probs @ V, epilogue splits to bf16 hi/lo ----------------
__global__ __launch_bounds__(256)
void pv_kernel(const float* __restrict__ qkv, const float* __restrict__ sc,
               __nv_bfloat16* __restrict__ o_hi, __nv_bfloat16* __restrict__ o_lo){
    int bh = blockIdx.x, it = blockIdx.y;
    int b = bh >> 4, hh = bh & 15;
    __shared__ float Ps[64][65];
    __shared__ float Vs[64][65];
    int t = threadIdx.x;
    int tx = t & 15, ty = t >> 4;
    float acc[4][4];
    #pragma unroll
    for (int i=0;i<4;i++)
        #pragma unroll
        for (int j=0;j<4;j++) acc[i][j]=0.f;
    const size_t vbase = (size_t)b * SEQ * 3 * DMODEL + 2*DMODEL + hh*HDIM;
    int kmax = (it + 1) * 64;
    for (int k0 = 0; k0 < kmax; k0 += 64){
        #pragma unroll
        for (int p = 0; p < 4; p++){
            int idx = t + p*256;
            int r = idx >> 4;
            int c = (idx & 15) * 4;
            float4 pv = *(const float4*)&sc[((size_t)bh*SEQ + it*64 + r)*SEQ + k0 + c];
            float4 vv = *(const float4*)&qkv[vbase + (size_t)(k0 + r)*3*DMODEL + c];
            Ps[r][c]=pv.x; Ps[r][c+1]=pv.y; Ps[r][c+2]=pv.z; Ps[r][c+3]=pv.w;
            Vs[r][c]=vv.x; Vs[r][c+1]=vv.y; Vs[r][c+2]=vv.z; Vs[r][c+3]=vv.w;
        }
        __syncthreads();
        #pragma unroll 8
        for (int kk = 0; kk < 64; kk++){
            float a[4], bb[4];
            #pragma unroll
            for (int i=0;i<4;i++) a[i]  = Ps[ty*4+i][kk];
            #pragma unroll
            for (int j=0;j<4;j++) bb[j] = Vs[kk][tx*4+j];
            #pragma unroll
            for (int i=0;i<4;i++)
                #pragma unroll
                for (int j=0;j<4;j++) acc[i][j] = fmaf(a[i], bb[j], acc[i][j]);
        }
        __syncthreads();
    }
    #pragma unroll
    for (int i=0;i<4;i++){
        int s = it*64 + ty*4 + i;
        uint16_t h0,l0,h1,l1,h2,l2,h3,l3;
        split_bf16(acc[i][0], h0, l0); split_bf16(acc[i][1], h1, l1);
        split_bf16(acc[i][2], h2, l2); split_bf16(acc[i][3], h3, l3);
        uint2 H, L;
        H.x = (uint32_t)h0 | ((uint32_t)h1 << 16);
        H.y = (uint32_t)h2 | ((uint32_t)h3 << 16);
        L.x = (uint32_t)l0 | ((uint32_t)l1 << 16);
        L.y = (uint32_t)l2 | ((uint32_t)l3 << 16);
        size_t base = ((size_t)b*SEQ + s)*DMODEL + hh*HDIM + tx*4;
        *(uint2*)&o_hi[base] = H;
        *(uint2*)&o_lo[base] = L;
    }
}

// ---------------- final projection ----------------
__global__ __launch_bounds__(256)
void pred_kernel(const float* __restrict__ hn, const float* __restrict__ Wp,
                 const float* __restrict__ bp, float* __restrict__ out){
    int row = blockIdx.x;
    int t = threadIdx.x;
    float local[WIN] = {0,0,0,0,0};
    const float* x = hn + (size_t)row * DMODEL;
    for (int k = t; k < DMODEL; k += 256){
        float xv = x[k];
        const float* wr = Wp + (size_t)k * WIN;
        #pragma unroll
        for (int w = 0; w < WIN; w++) local[w] = fmaf(xv, wr[w], local[w]);
    }
    __shared__ float red[WIN][256];
    #pragma unroll
    for (int w = 0; w < WIN; w++) red[w][t] = local[w];
    __syncthreads();
    for (int s = 128; s > 0; s >>= 1){
        if (t < s){
            #pragma unroll
            for (int w = 0; w < WIN; w++) red[w][t] += red[w][t + s];
        }
        __syncthreads();
    }
    if (t < WIN) out[(size_t)row * WIN + t] = red[t][0] + bp[t];
}

// ---------------- host orchestration ----------------
extern "C" void kernel_launch(void* const* d_in, const int* in_sizes, int n_in,
                              void* d_out, int out_size){
    const float* x     = (const float*)d_in[0];
    const float* Wqkv  = (const float*)d_in[1];
    const float* bqkv  = (const float*)d_in[2];
    const float* Wo    = (const float*)d_in[3];
    const float* bo    = (const float*)d_in[4];
    const float* ln1w  = (const float*)d_in[5];
    const float* ln1b  = (const float*)d_in[6];
    const float* W1    = (const float*)d_in[7];
    const float* b1    = (const float*)d_in[8];
    const float* W2    = (const float*)d_in[9];
    const float* b2    = (const float*)d_in[10];
    const float* ln2w  = (const float*)d_in[11];
    const float* ln2b  = (const float*)d_in[12];
    const float* lnfw  = (const float*)d_in[13];
    const float* lnfb  = (const float*)d_in[14];
    const float* Wp    = (const float*)d_in[15];
    const float* bp    = (const float*)d_in[16];
    float* out = (float*)d_out;

    float *g_h, *g_hn, *g_qkv, *g_sc;
    __nv_bfloat16 *g_hn_hi, *g_hn_lo, *g_o_hi, *g_o_lo, *g_ff_hi, *g_ff_lo, *g_w_hi, *g_w_lo;
    cudaGetSymbolAddress((void**)&g_h,     d_h);
    cudaGetSymbolAddress((void**)&g_hn,    d_hn);
    cudaGetSymbolAddress((void**)&g_hn_hi, d_hn_hi);
    cudaGetSymbolAddress((void**)&g_hn_lo, d_hn_lo);
    cudaGetSymbolAddress((void**)&g_qkv,   d_qkv);
    cudaGetSymbolAddress((void**)&g_o_hi,  d_o_hi);
    cudaGetSymbolAddress((void**)&g_o_lo,  d_o_lo);
    cudaGetSymbolAddress((void**)&g_ff_hi, d_ff_hi);
    cudaGetSymbolAddress((void**)&g_ff_lo, d_ff_lo);
    cudaGetSymbolAddress((void**)&g_sc,    d_sc);
    cudaGetSymbolAddress((void**)&g_w_hi,  d_w_hi);
    cudaGetSymbolAddress((void**)&g_w_lo,  d_w_lo);

    cudaFuncSetAttribute(gemm_bf16x3<0>, cudaFuncAttributeMaxDynamicSharedMemorySize, GEMM_SMEM);
    cudaFuncSetAttribute(gemm_bf16x3<1>, cudaFuncAttributeMaxDynamicSharedMemorySize, GEMM_SMEM);
    cudaFuncSetAttribute(gemm_bf16x3<2>, cudaFuncAttributeMaxDynamicSharedMemorySize, GEMM_SMEM);

    // pre-split all weights into bf16 hi/lo
    wsplit_kernel<<<QKV_ELEMS/4/256, 256>>>((const float4*)Wqkv,
        (uint2*)(g_w_hi + QKV_OFF), (uint2*)(g_w_lo + QKV_OFF), QKV_ELEMS/4);
    wsplit_kernel<<<WO_ELEMS/4/256, 256>>>((const float4*)Wo,
        (uint2*)(g_w_hi + WO_OFF),  (uint2*)(g_w_lo + WO_OFF),  WO_ELEMS/4);
    wsplit_kernel<<<W1_ELEMS/4/256, 256>>>((const float4*)W1,
        (uint2*)(g_w_hi + W1_OFF),  (uint2*)(g_w_lo + W1_OFF),  W1_ELEMS/4);
    wsplit_kernel<<<W2_ELEMS/4/256, 256>>>((const float4*)W2,
        (uint2*)(g_w_hi + W2_OFF),  (uint2*)(g_w_lo + W2_OFF),  W2_ELEMS/4);

    copy_kernel<<<TOKENS*DMODEL/4/256, 256>>>(x, g_h);

    for (int l = 0; l < LAYERS; l++){
        const __nv_bfloat16* wqkv_h = g_w_hi + QKV_OFF + (size_t)l * DMODEL * 3*DMODEL;
        const __nv_bfloat16* wqkv_l = g_w_lo + QKV_OFF + (size_t)l * DMODEL * 3*DMODEL;
        const __nv_bfloat16* wo_h   = g_w_hi + WO_OFF  + (size_t)l * DMODEL * DMODEL;
        const __nv_bfloat16* wo_l   = g_w_lo + WO_OFF  + (size_t)l * DMODEL * DMODEL;
        const __nv_bfloat16* w1_h   = g_w_hi + W1_OFF  + (size_t)l * DMODEL * DFF;
        const __nv_bfloat16* w1_l   = g_w_lo + W1_OFF  + (size_t)l * DMODEL * DFF;
        const __nv_bfloat16* w2_h   = g_w_hi + W2_OFF  + (size_t)l * DFF * DMODEL;
        const __nv_bfloat16* w2_l   = g_w_lo + W2_OFF  + (size_t)l * DFF * DMODEL;
        const float* bq = bqkv + (size_t)l * 3*DMODEL;
        const float* bO = bo   + (size_t)l * DMODEL;
        const float* B1 = b1   + (size_t)l * DFF;
        const float* B2 = b2   + (size_t)l * DMODEL;

        // pre-norm attention
        ln_kernel<<<TOKENS, 256>>>(g_h, ln1w + l*DMODEL, ln1b + l*DMODEL,
                                   g_hn, g_hn_hi, g_hn_lo);
        gemm_bf16x3<0><<<dim3(3*DMODEL/128, TOKENS/128), 256, GEMM_SMEM>>>(
            g_hn_hi, g_hn_lo, wqkv_h, wqkv_l, bq, nullptr,
            g_qkv, nullptr, nullptr, TOKENS, 3*DMODEL, DMODEL);
        scores_kernel <<<dim3(BATCH*NHEAD, SEQ/64, SEQ/64), 256>>>(g_qkv, g_sc);
        softmax_kernel<<<dim3(BATCH*NHEAD, SEQ), 256>>>(g_sc);
        pv_kernel     <<<dim3(BATCH*NHEAD, SEQ/64), 256>>>(g_qkv, g_sc, g_o_hi, g_o_lo);
        gemm_bf16x3<1><<<dim3(DMODEL/128, TOKENS/128), 256, GEMM_SMEM>>>(
            g_o_hi, g_o_lo, wo_h, wo_l, bO, g_h,
            g_h, nullptr, nullptr, TOKENS, DMODEL, DMODEL);

        // pre-norm FFN
        ln_kernel<<<TOKENS, 256>>>(g_h, ln2w + l*DMODEL, ln2b + l*DMODEL,
                                   g_hn, g_hn_hi, g_hn_lo);
        gemm_bf16x3<2><<<dim3(DFF/128, TOKENS/128), 256, GEMM_SMEM>>>(
            g_hn_hi, g_hn_lo, w1_h, w1_l, B1, nullptr,
            nullptr, g_ff_hi, g_ff_lo, TOKENS, DFF, DMODEL);
        gemm_bf16x3<1><<<dim3(DMODEL/128, TOKENS/128), 256, GEMM_SMEM>>>(
            g_ff_hi, g_ff_lo, w2_h, w2_l, B2, g_h,
            g_h, nullptr, nullptr, TOKENS, DMODEL, DFF);
    }

    // final LN + projection
    ln_kernel<<<TOKENS, 256>>>(g_h, lnfw, lnfb, g_hn, g_hn_hi, g_hn_lo);
    pred_kernel<<<TOKENS, 256>>>(g_hn, Wp, bp, out);
    (void)in_sizes; (void)n_in; (void)out_size;
}

// round 4
// speedup vs baseline: 3.0312x; 1.3386x over previous
#include <cuda_runtime.h>
#include <cuda_bf16.h>
#include <math.h>
#include <stdint.h>

// ---------------- problem constants ----------------
#define LAYERS 6
#define BATCH  2
#define SEQ    1024
#define DMODEL 1024
#define NHEAD  16
#define HDIM   64
#define DFF    4096
#define WIN    5
#define TOKENS (BATCH*SEQ)          // 2048
#define EPS    1e-5f

// weight scratch layout (elements)
#define QKV_ELEMS  (LAYERS*DMODEL*3*DMODEL)
#define WO_ELEMS   (LAYERS*DMODEL*DMODEL)
#define W1_ELEMS   (LAYERS*DMODEL*DFF)
#define W2_ELEMS   (LAYERS*DFF*DMODEL)
#define QKV_OFF 0
#define WO_OFF  (QKV_ELEMS)
#define W1_OFF  (WO_OFF + WO_ELEMS)
#define W2_OFF  (W1_OFF + W1_ELEMS)
#define WTOTAL  (W2_OFF + W2_ELEMS)

// ---------------- device scratch (no allocation allowed) ----------------
__device__ float d_h   [TOKENS*DMODEL];
__device__ float d_hn  [TOKENS*DMODEL];
__device__ __nv_bfloat16 d_hn_hi[TOKENS*DMODEL];
__device__ __nv_bfloat16 d_hn_lo[TOKENS*DMODEL];
__device__ __nv_bfloat16 d_qkv_hi[TOKENS*3*DMODEL];
__device__ __nv_bfloat16 d_qkv_lo[TOKENS*3*DMODEL];
__device__ __nv_bfloat16 d_o_hi[TOKENS*DMODEL];
__device__ __nv_bfloat16 d_o_lo[TOKENS*DMODEL];
__device__ __nv_bfloat16 d_ff_hi[TOKENS*DFF];
__device__ __nv_bfloat16 d_ff_lo[TOKENS*DFF];
__device__ __nv_bfloat16 d_w_hi[WTOTAL];
__device__ __nv_bfloat16 d_w_lo[WTOTAL];

// ---------------- small helpers ----------------
__device__ __forceinline__ float warp_sum(float v){
    #pragma unroll
    for (int o = 16; o; o >>= 1) v += __shfl_xor_sync(0xffffffffu, v, o);
    return v;
}
__device__ __forceinline__ float gelu_exact(float x){
    return 0.5f * x * (1.0f + erff(x * 0.70710678118654752440f));
}
__device__ __forceinline__ uint32_t smem_u32(const void* p){
    uint32_t a;
    asm("{ .reg .u64 t; cvta.to.shared.u64 t, %1; cvt.u32.u64 %0, t; }" : "=r"(a) : "l"(p));
    return a;
}
__device__ __forceinline__ void split_bf16(float x, uint16_t& hi, uint16_t& lo){
    uint32_t u  = __float_as_uint(x);
    uint32_t hu = u & 0xFFFF0000u;
    hi = (uint16_t)(hu >> 16);
    float l = x - __uint_as_float(hu);
    lo = __bfloat16_as_ushort(__float2bfloat16(l));
}
// pack hi-bf16 halves of two fp32 into one u32 (x -> low half)
__device__ __forceinline__ uint32_t pack_hi2(float x, float y){
    return (__float_as_uint(x) >> 16) | (__float_as_uint(y) & 0xFFFF0000u);
}
__device__ __forceinline__ uint32_t pack_lo2(float x, float y){
    float lx = x - __uint_as_float(__float_as_uint(x) & 0xFFFF0000u);
    float ly = y - __uint_as_float(__float_as_uint(y) & 0xFFFF0000u);
    __nv_bfloat162 t = __floats2bfloat162_rn(lx, ly);
    return *reinterpret_cast<uint32_t*>(&t);
}

// ---------------- mma.sync / ldmatrix / cp.async wrappers ----------------
__device__ __forceinline__ void mma_bf16(float* d, const uint32_t* a, const uint32_t* b){
    asm volatile(
      "mma.sync.aligned.m16n8k16.row.col.f32.bf16.bf16.f32 "
      "{%0,%1,%2,%3}, {%4,%5,%6,%7}, {%8,%9}, {%0,%1,%2,%3};\n"
      : "+f"(d[0]), "+f"(d[1]), "+f"(d[2]), "+f"(d[3])
      : "r"(a[0]), "r"(a[1]), "r"(a[2]), "r"(a[3]), "r"(b[0]), "r"(b[1]));
}
__device__ __forceinline__ void ldsm_x4(uint32_t* r, uint32_t addr){
    asm volatile("ldmatrix.sync.aligned.m8n8.x4.shared.b16 {%0,%1,%2,%3}, [%4];"
      : "=r"(r[0]), "=r"(r[1]), "=r"(r[2]), "=r"(r[3]) : "r"(addr));
}
__device__ __forceinline__ void ldsm_x2(uint32_t* r, uint32_t addr){
    asm volatile("ldmatrix.sync.aligned.m8n8.x2.shared.b16 {%0,%1}, [%2];"
      : "=r"(r[0]), "=r"(r[1]) : "r"(addr));
}
__device__ __forceinline__ void ldsm_x2t(uint32_t* r, uint32_t addr){
    asm volatile("ldmatrix.sync.aligned.m8n8.x2.trans.shared.b16 {%0,%1}, [%2];"
      : "=r"(r[0]), "=r"(r[1]) : "r"(addr));
}
__device__ __forceinline__ void cp16(uint32_t s, const void* g){
    asm volatile("cp.async.cg.shared.global [%0], [%1], 16;\n" :: "r"(s), "l"(g));
}

// ---------------- GEMM smem layout ----------------
#define KC          32
#define A_STRIDE    80
#define B_STRIDE    272
#define A_LO_OFF    10240
#define B_OFF       20480
#define B_LO_OFF    8704
#define STAGE_BYTES 37888
#define GEMM_SMEM   (3*STAGE_BYTES)

__device__ __forceinline__ void issue_stage(
    const __nv_bfloat16* __restrict__ Ah, const __nv_bfloat16* __restrict__ Al,
    const __nv_bfloat16* __restrict__ Bh, const __nv_bfloat16* __restrict__ Bl,
    uint32_t sb0, int tid, int m0, int n0, int K, int N, int c)
{
    uint32_t sb = sb0 + (uint32_t)(c % 3) * STAGE_BYTES;
    int k0 = c * KC;
    #pragma unroll
    for (int i = 0; i < 2; i++){
        int idx = tid + i*256;
        int r = idx >> 2, cc = idx & 3;
        uint32_t sa = sb + r*A_STRIDE + cc*16;
        size_t g = (size_t)(m0 + r) * K + k0 + cc*8;
        cp16(sa,            Ah + g);
        cp16(sa + A_LO_OFF, Al + g);
    }
    #pragma unroll
    for (int i = 0; i < 2; i++){
        int idx = tid + i*256;
        int r = idx >> 4, cc = idx & 15;
        uint32_t sa = sb + B_OFF + r*B_STRIDE + cc*16;
        size_t g = (size_t)(k0 + r) * N + n0 + cc*8;
        cp16(sa,            Bh + g);
        cp16(sa + B_LO_OFF, Bl + g);
    }
    asm volatile("cp.async.commit_group;");
}

// =====================================================================
// bf16x3 emulated-fp32 GEMM:  C[M,N] = epi(A @ B + bias)
// EPI: 0 = bias (f32)  1 = bias+residual (f32)
//      2 = bias+GELU -> split bf16 hi/lo   3 = bias -> split bf16 hi/lo
// =====================================================================
template<int EPI>
__global__ __launch_bounds__(256)
void gemm_bf16x3(const __nv_bfloat16* __restrict__ Ah, const __nv_bfloat16* __restrict__ Al,
                 const __nv_bfloat16* __restrict__ Bh, const __nv_bfloat16* __restrict__ Bl,
                 const float* __restrict__ bias, const float* __restrict__ res,
                 float* __restrict__ C,
                 __nv_bfloat16* __restrict__ Chi, __nv_bfloat16* __restrict__ Clo,
                 int M, int N, int K)
{
    extern __shared__ char smem[];
    const uint32_t sb0 = smem_u32(smem);
    const int tid  = threadIdx.x;
    const int lane = tid & 31, wid = tid >> 5;
    const int m0 = blockIdx.y * 128, n0 = blockIdx.x * 128;
    const int wm = (wid >> 2) * 64, wn = (wid & 3) * 32;

    float acc[4][4][4];
    #pragma unroll
    for (int a = 0; a < 4; a++)
        #pragma unroll
        for (int b = 0; b < 4; b++)
            #pragma unroll
            for (int cc = 0; cc < 4; cc++) acc[a][b][cc] = 0.f;

    const int nch = K / KC;
    issue_stage(Ah, Al, Bh, Bl, sb0, tid, m0, n0, K, N, 0);
    issue_stage(Ah, Al, Bh, Bl, sb0, tid, m0, n0, K, N, 1);

    const uint32_t a_lrow = wm + (lane & 15);
    const uint32_t a_lcol = (lane >> 4) * 8;
    const uint32_t b_lrow = (lane & 15);

    for (int c = 0; c < nch; c++){
        if (c + 2 < nch) issue_stage(Ah, Al, Bh, Bl, sb0, tid, m0, n0, K, N, c + 2);
        else asm volatile("cp.async.commit_group;");
        asm volatile("cp.async.wait_group %0;" :: "n"(2));
        __syncthreads();

        uint32_t sb = sb0 + (uint32_t)(c % 3) * STAGE_BYTES;
        #pragma unroll
        for (int ks = 0; ks < 2; ks++){
            uint32_t ah[4][4], al[4][4], bh[4][2], bl[4][2];
            #pragma unroll
            for (int mt = 0; mt < 4; mt++){
                uint32_t ad = sb + (a_lrow + mt*16)*A_STRIDE + (ks*16 + a_lcol)*2;
                ldsm_x4(ah[mt], ad);
                ldsm_x4(al[mt], ad + A_LO_OFF);
            }
            #pragma unroll
            for (int nt = 0; nt < 4; nt++){
                uint32_t bd = sb + B_OFF + (ks*16 + b_lrow)*B_STRIDE + (wn + nt*8)*2;
                ldsm_x2t(bh[nt], bd);
                ldsm_x2t(bl[nt], bd + B_LO_OFF);
            }
            #pragma unroll
            for (int mt = 0; mt < 4; mt++)
                #pragma unroll
                for (int nt = 0; nt < 4; nt++){
                    mma_bf16(acc[mt][nt], ah[mt], bh[nt]);
                    mma_bf16(acc[mt][nt], ah[mt], bl[nt]);
                    mma_bf16(acc[mt][nt], al[mt], bh[nt]);
                }
        }
        __syncthreads();
    }

    // ---- epilogue ----
    const int g  = lane >> 2;
    const int tq = (lane & 3) * 2;
    #pragma unroll
    for (int mt = 0; mt < 4; mt++){
        #pragma unroll
        for (int half = 0; half < 2; half++){
            int m = m0 + wm + mt*16 + g + half*8;
            #pragma unroll
            for (int nt = 0; nt < 4; nt++){
                int n = n0 + wn + nt*8 + tq;
                float v0 = acc[mt][nt][half*2+0] + bias[n];
                float v1 = acc[mt][nt][half*2+1] + bias[n+1];
                size_t gi = (size_t)m * N + n;
                if (EPI == 1){ v0 += res[gi]; v1 += res[gi+1]; }
                if (EPI >= 2){
                    if (EPI == 2){ v0 = gelu_exact(v0); v1 = gelu_exact(v1); }
                    *(uint32_t*)&Chi[gi] = pack_hi2(v0, v1);
                    *(uint32_t*)&Clo[gi] = pack_lo2(v0, v1);
                } else {
                    float2 o; o.x = v0; o.y = v1;
                    *(float2*)&C[gi] = o;
                }
            }
        }
    }
}

// =====================================================================
// Flash attention, bf16x3, causal.  Bq=128 (8 warps x 16 rows), Bc=64.
// qkv hi/lo layout: [token][3*DMODEL]; Q at h*64, K at D+h*64, V at 2D+h*64.
// Writes o hi/lo split [token][DMODEL].
// smem: Qhi 0 (18432) Qlo 18432 | stage s at 36864+s*36864:
//       Khi +0, Klo +9216, Vhi +18432, Vlo +27648  (9216 each)
// row stride 144B (72 bf16) - conflict-free for ldmatrix.
// =====================================================================
#define FL_SMEM 110592

__global__ __launch_bounds__(256)
void flash_kernel(const __nv_bfloat16* __restrict__ qkv_hi,
                  const __nv_bfloat16* __restrict__ qkv_lo,
                  __nv_bfloat16* __restrict__ o_hi,
                  __nv_bfloat16* __restrict__ o_lo)
{
    extern __shared__ char fsm[];
    const uint32_t sb = smem_u32(fsm);
    const int tid = threadIdx.x, lane = tid & 31, w = tid >> 5;
    const int bh = blockIdx.x;
    const int it = 7 - blockIdx.y;           // heavy q-tiles first
    const int b = bh >> 4, h = bh & 15;
    const int nk = 2*(it+1);
    const size_t rs = 3*DMODEL;

    // ---- issue Q loads (group 0) ----
    {
        const size_t tok0 = (size_t)(b*SEQ + it*128);
        #pragma unroll
        for (int i = 0; i < 4; i++){
            int idx = tid + i*256;
            int r = idx >> 3, c = idx & 7;
            size_t g = (tok0 + r)*rs + h*64 + c*8;
            uint32_t sa = sb + r*144 + c*16;
            cp16(sa,         qkv_hi + g);
            cp16(sa + 18432, qkv_lo + g);
        }
        asm volatile("cp.async.commit_group;");
    }
    // ---- KV tile issue ----
    #define ISSUE_KV(jt_) do {                                               \
        uint32_t st_ = sb + 36864u + (uint32_t)((jt_)&1)*36864u;             \
        const size_t tok0_ = (size_t)(b*SEQ + (jt_)*64);                     \
        _Pragma("unroll")                                                    \
        for (int i_ = 0; i_ < 2; i_++){                                      \
            int idx_ = tid + i_*256;                                         \
            int r_ = idx_ >> 3, c_ = idx_ & 7;                               \
            size_t gk_ = (tok0_ + r_)*rs + DMODEL   + h*64 + c_*8;           \
            size_t gv_ = (tok0_ + r_)*rs + 2*DMODEL + h*64 + c_*8;           \
            uint32_t sa_ = st_ + r_*144 + c_*16;                             \
            cp16(sa_,         qkv_hi + gk_);                                 \
            cp16(sa_ + 9216,  qkv_lo + gk_);                                 \
            cp16(sa_ + 18432, qkv_hi + gv_);                                 \
            cp16(sa_ + 27648, qkv_lo + gv_);                                 \
        }                                                                    \
        asm volatile("cp.async.commit_group;");                              \
    } while(0)

    ISSUE_KV(0);
    asm volatile("cp.async.wait_group 1;");   // Q ready
    __syncthreads();

    // ---- Q fragments (held in registers for whole kernel) ----
    uint32_t qh[4][4], ql[4][4];
    {
        uint32_t rbase = sb + (w*16 + (lane & 15))*144 + ((lane >> 4)*8)*2;
        #pragma unroll
        for (int ks = 0; ks < 4; ks++){
            ldsm_x4(qh[ks], rbase + ks*32);
            ldsm_x4(ql[ks], rbase + ks*32 + 18432);
        }
    }

    float O[8][4];
    #pragma unroll
    for (int nt = 0; nt < 8; nt++)
        #pragma unroll
        for (int c = 0; c < 4; c++) O[nt][c] = 0.f;
    float m0 = -INFINITY, m1 = -INFINITY, l0 = 0.f, l1 = 0.f;
    const int r0g = it*128 + w*16 + (lane >> 2);   // global row of half 0

    for (int jt = 0; jt < nk; jt++){
        if (jt + 1 < nk){ ISSUE_KV(jt+1); asm volatile("cp.async.wait_group 1;"); }
        else            { asm volatile("cp.async.wait_group 0;"); }
        __syncthreads();
        const uint32_t st = sb + 36864u + (uint32_t)(jt&1)*36864u;

        // ---- S = scale * Q K^T ----
        float S[8][4];
        #pragma unroll
        for (int nt = 0; nt < 8; nt++)
            #pragma unroll
            for (int c = 0; c < 4; c++) S[nt][c] = 0.f;

        const uint32_t kb = st + (lane & 7)*144 + (((lane >> 3) & 1)*8)*2;
        #pragma unroll
        for (int nt = 0; nt < 8; nt++){
            #pragma unroll
            for (int ks = 0; ks < 4; ks++){
                uint32_t a = kb + nt*8*144 + ks*32;
                uint32_t kh[2], kl[2];
                ldsm_x2(kh, a);
                ldsm_x2(kl, a + 9216);
                mma_bf16(S[nt], qh[ks], kh);
                mma_bf16(S[nt], qh[ks], kl);
                mma_bf16(S[nt], ql[ks], kh);
            }
        }

        // ---- mask + scale + online softmax ----
        const bool diag = (jt >= 2*it);
        float mx0 = -INFINITY, mx1 = -INFINITY;
        #pragma unroll
        for (int nt = 0; nt < 8; nt++){
            int colb = jt*64 + nt*8 + (lane & 3)*2;
            #pragma unroll
            for (int q = 0; q < 2; q++){
                float v0 = S[nt][q]   * 0.125f;
                float v1 = S[nt][2+q] * 0.125f;
                if (diag){
                    if (colb + q > r0g)     v0 = -INFINITY;
                    if (colb + q > r0g + 8) v1 = -INFINITY;
                }
                S[nt][q] = v0; S[nt][2+q] = v1;
                mx0 = fmaxf(mx0, v0); mx1 = fmaxf(mx1, v1);
            }
        }
        mx0 = fmaxf(mx0, __shfl_xor_sync(0xffffffffu, mx0, 1));
        mx0 = fmaxf(mx0, __shfl_xor_sync(0xffffffffu, mx0, 2));
        mx1 = fmaxf(mx1, __shfl_xor_sync(0xffffffffu, mx1, 1));
        mx1 = fmaxf(mx1, __shfl_xor_sync(0xffffffffu, mx1, 2));
        float mn0 = fmaxf(m0, mx0), mn1 = fmaxf(m1, mx1);
        float f0 = __expf(m0 - mn0), f1 = __expf(m1 - mn1);
        m0 = mn0; m1 = mn1;
        float ls0 = 0.f, ls1 = 0.f;
        #pragma unroll
        for (int nt = 0; nt < 8; nt++){
            #pragma unroll
            for (int q = 0; q < 2; q++){
                float e0 = __expf(S[nt][q]   - m0);
                float e1 = __expf(S[nt][2+q] - m1);
                S[nt][q] = e0; S[nt][2+q] = e1;
                ls0 += e0; ls1 += e1;
            }
        }
        l0 = l0*f0 + ls0;        // per-lane partial; reduced at the end
        l1 = l1*f1 + ls1;
        #pragma unroll
        for (int nt = 0; nt < 8; nt++){
            O[nt][0] *= f0; O[nt][1] *= f0;
            O[nt][2] *= f1; O[nt][3] *= f1;
        }

        // ---- O += P V ----
        #pragma unroll
        for (int ks = 0; ks < 4; ks++){
            uint32_t ph[4], pl[4];
            ph[0] = pack_hi2(S[2*ks][0],   S[2*ks][1]);
            ph[1] = pack_hi2(S[2*ks][2],   S[2*ks][3]);
            ph[2] = pack_hi2(S[2*ks+1][0], S[2*ks+1][1]);
            ph[3] = pack_hi2(S[2*ks+1][2], S[2*ks+1][3]);
            pl[0] = pack_lo2(S[2*ks][0],   S[2*ks][1]);
            pl[1] = pack_lo2(S[2*ks][2],   S[2*ks][3]);
            pl[2] = pack_lo2(S[2*ks+1][0], S[2*ks+1][1]);
            pl[3] = pack_lo2(S[2*ks+1][2], S[2*ks+1][3]);
            uint32_t vb = st + 18432u + (ks*16 + (lane & 15))*144;
            #pragma unroll
            for (int nt = 0; nt < 8; nt++){
                uint32_t vh[2], vl[2];
                ldsm_x2t(vh, vb + nt*16);
                ldsm_x2t(vl, vb + nt*16 + 9216);
                mma_bf16(O[nt], ph, vh);
                mma_bf16(O[nt], ph, vl);
                mma_bf16(O[nt], pl, vh);
            }
        }
        __syncthreads();   // protect buffer (jt&1) before re-issue
    }

    // ---- finalize: divide by l, split, store ----
    l0 += __shfl_xor_sync(0xffffffffu, l0, 1);
    l0 += __shfl_xor_sync(0xffffffffu, l0, 2);
    l1 += __shfl_xor_sync(0xffffffffu, l1, 1);
    l1 += __shfl_xor_sync(0xffffffffu, l1, 2);
    float inv0 = 1.0f / l0, inv1 = 1.0f / l1;
    const size_t tok0 = (size_t)(b*SEQ + it*128 + w*16 + (lane >> 2));
    const int colb = h*64 + (lane & 3)*2;
    #pragma unroll
    for (int nt = 0; nt < 8; nt++){
        #pragma unroll
        for (int rh = 0; rh < 2; rh++){
            float inv = rh ? inv1 : inv0;
            float v0 = O[nt][rh*2+0] * inv;
            float v1 = O[nt][rh*2+1] * inv;
            size_t gi = (tok0 + rh*8)*DMODEL + colb + nt*8;
            *(uint32_t*)&o_hi[gi] = pack_hi2(v0, v1);
            *(uint32_t*)&o_lo[gi] = pack_lo2(v0, v1);
        }
    }
}

// ---------------- weight split: fp32 -> bf16 hi/lo ----------------
__global__ void wsplit_kernel(const float4* __restrict__ in,
                              uint2* __restrict__ hi, uint2* __restrict__ lo, int n4){
    int i = blockIdx.x * blockDim.x + threadIdx.x;
    if (i >= n4) return;
    float4 v = in[i];
    uint16_t h0,l0,h1,l1,h2,l2,h3,l3;
    split_bf16(v.x, h0, l0); split_bf16(v.y, h1, l1);
    split_bf16(v.z, h2, l2); split_bf16(v.w, h3, l3);
    uint2 H, L;
    H.x = (uint32_t)h0 | ((uint32_t)h1 << 16);
    H.y = (uint32_t)h2 | ((uint32_t)h3 << 16);
    L.x = (uint32_t)l0 | ((uint32_t)l1 << 16);
    L.y = (uint32_t)l2 | ((uint32_t)l3 << 16);
    hi[i] = H; lo[i] = L;
}

// ---------------- copy x -> h ----------------
__global__ void copy_kernel(const float* __restrict__ in, float* __restrict__ out){
    int idx = blockIdx.x * blockDim.x + threadIdx.x;
    float4 v = ((const float4*)in)[idx];
    ((float4*)out)[idx] = v;
}

// ---------------- LayerNorm (writes fp32 + bf16 hi/lo) ----------------
__global__ void ln_kernel(const float* __restrict__ in,
                          const float* __restrict__ w,
                          const float* __restrict__ b,
                          float* __restrict__ out,
                          __nv_bfloat16* __restrict__ out_hi,
                          __nv_bfloat16* __restrict__ out_lo){
    int row = blockIdx.x;
    int t   = threadIdx.x;
    const float* x = in + (size_t)row * DMODEL;
    float4 v = *(const float4*)&x[t*4];
    float s  = v.x + v.y + v.z + v.w;
    float sq = v.x*v.x + v.y*v.y + v.z*v.z + v.w*v.w;
    s  = warp_sum(s);
    sq = warp_sum(sq);
    __shared__ float sh1[8], sh2[8];
    int warp = t >> 5, lane = t & 31;
    if (lane == 0){ sh1[warp] = s; sh2[warp] = sq; }
    __syncthreads();
    float tot = 0.f, tot2 = 0.f;
    #pragma unroll
    for (int i = 0; i < 8; i++){ tot += sh1[i]; tot2 += sh2[i]; }
    float mu   = tot  * (1.0f/DMODEL);
    float var  = tot2 * (1.0f/DMODEL) - mu*mu;
    float rstd = rsqrtf(var + EPS);
    float4 wv = *(const float4*)&w[t*4];
    float4 bv = *(const float4*)&b[t*4];
    float4 ov;
    ov.x = (v.x - mu)*rstd*wv.x + bv.x;
    ov.y = (v.y - mu)*rstd*wv.y + bv.y;
    ov.z = (v.z - mu)*rstd*wv.z + bv.z;
    ov.w = (v.w - mu)*rstd*wv.w + bv.w;
    size_t base = (size_t)row*DMODEL + t*4;
    *(float4*)&out[base] = ov;
    uint2 H, L;
    H.x = pack_hi2(ov.x, ov.y); H.y = pack_hi2(ov.z, ov.w);
    L.x = pack_lo2(ov.x, ov.y); L.y = pack_lo2(ov.z, ov.w);
    *(uint2*)&out_hi[base] = H;
    *(uint2*)&out_lo[base] = L;
}

// ---------------- final projection ----------------
__global__ __launch_bounds__(256)
void pred_kernel(const float* __restrict__ hn, const float* __restrict__ Wp,
                 const float* __restrict__ bp, float* __restrict__ out){
    int row = blockIdx.x;
    int t = threadIdx.x;
    float local[WIN] = {0,0,0,0,0};
    const float* x = hn + (size_t)row * DMODEL;
    for (int k = t; k < DMODEL; k += 256){
        float xv = x[k];
        const float* wr = Wp + (size_t)k * WIN;
        #pragma unroll
        for (int w = 0; w < WIN; w++) local[w] = fmaf(xv, wr[w], local[w]);
    }
    __shared__ float red[WIN][256];
    #pragma unroll
    for (int w = 0; w < WIN; w++) red[w][t] = local[w];
    __syncthreads();
    for (int s = 128; s > 0; s >>= 1){
        if (t < s){
            #pragma unroll
            for (int w = 0; w < WIN; w++) red[w][t] += red[w][t + s];
        }
        __syncthreads();
    }
    if (t < WIN) out[(size_t)row * WIN + t] = red[t][0] + bp[t];
}

// ---------------- host orchestration ----------------
extern "C" void kernel_launch(void* const* d_in, const int* in_sizes, int n_in,
                              void* d_out, int out_size){
    const float* x     = (const float*)d_in[0];
    const float* Wqkv  = (const float*)d_in[1];
    const float* bqkv  = (const float*)d_in[2];
    const float* Wo    = (const float*)d_in[3];
    const float* bo    = (const float*)d_in[4];
    const float* ln1w  = (const float*)d_in[5];
    const float* ln1b  = (const float*)d_in[6];
    const float* W1    = (const float*)d_in[7];
    const float* b1    = (const float*)d_in[8];
    const float* W2    = (const float*)d_in[9];
    const float* b2    = (const float*)d_in[10];
    const float* ln2w  = (const float*)d_in[11];
    const float* ln2b  = (const float*)d_in[12];
    const float* lnfw  = (const float*)d_in[13];
    const float* lnfb  = (const float*)d_in[14];
    const float* Wp    = (const float*)d_in[15];
    const float* bp    = (const float*)d_in[16];
    float* out = (float*)d_out;

    float *g_h, *g_hn;
    __nv_bfloat16 *g_hn_hi, *g_hn_lo, *g_qkv_hi, *g_qkv_lo,
                  *g_o_hi, *g_o_lo, *g_ff_hi, *g_ff_lo, *g_w_hi, *g_w_lo;
    cudaGetSymbolAddress((void**)&g_h,      d_h);
    cudaGetSymbolAddress((void**)&g_hn,     d_hn);
    cudaGetSymbolAddress((void**)&g_hn_hi,  d_hn_hi);
    cudaGetSymbolAddress((void**)&g_hn_lo,  d_hn_lo);
    cudaGetSymbolAddress((void**)&g_qkv_hi, d_qkv_hi);
    cudaGetSymbolAddress((void**)&g_qkv_lo, d_qkv_lo);
    cudaGetSymbolAddress((void**)&g_o_hi,   d_o_hi);
    cudaGetSymbolAddress((void**)&g_o_lo,   d_o_lo);
    cudaGetSymbolAddress((void**)&g_ff_hi,  d_ff_hi);
    cudaGetSymbolAddress((void**)&g_ff_lo,  d_ff_lo);
    cudaGetSymbolAddress((void**)&g_w_hi,   d_w_hi);
    cudaGetSymbolAddress((void**)&g_w_lo,   d_w_lo);

    cudaFuncSetAttribute(gemm_bf16x3<0>, cudaFuncAttributeMaxDynamicSharedMemorySize, GEMM_SMEM);
    cudaFuncSetAttribute(gemm_bf16x3<1>, cudaFuncAttributeMaxDynamicSharedMemorySize, GEMM_SMEM);
    cudaFuncSetAttribute(gemm_bf16x3<2>, cudaFuncAttributeMaxDynamicSharedMemorySize, GEMM_SMEM);
    cudaFuncSetAttribute(gemm_bf16x3<3>, cudaFuncAttributeMaxDynamicSharedMemorySize, GEMM_SMEM);
    cudaFuncSetAttribute(flash_kernel,   cudaFuncAttributeMaxDynamicSharedMemorySize, FL_SMEM);

    // pre-split all weights into bf16 hi/lo
    wsplit_kernel<<<QKV_ELEMS/4/256, 256>>>((const float4*)Wqkv,
        (uint2*)(g_w_hi + QKV_OFF), (uint2*)(g_w_lo + QKV_OFF), QKV_ELEMS/4);
    wsplit_kernel<<<WO_ELEMS/4/256, 256>>>((const float4*)Wo,
        (uint2*)(g_w_hi + WO_OFF),  (uint2*)(g_w_lo + WO_OFF),  WO_ELEMS/4);
    wsplit_kernel<<<W1_ELEMS/4/256, 256>>>((const float4*)W1,
        (uint2*)(g_w_hi + W1_OFF),  (uint2*)(g_w_lo + W1_OFF),  W1_ELEMS/4);
    wsplit_kernel<<<W2_ELEMS/4/256, 256>>>((const float4*)W2,
        (uint2*)(g_w_hi + W2_OFF),  (uint2*)(g_w_lo + W2_OFF),  W2_ELEMS/4);

    copy_kernel<<<TOKENS*DMODEL/4/256, 256>>>(x, g_h);

    for (int l = 0; l < LAYERS; l++){
        const __nv_bfloat16* wqkv_h = g_w_hi + QKV_OFF + (size_t)l * DMODEL * 3*DMODEL;
        const __nv_bfloat16* wqkv_l = g_w_lo + QKV_OFF + (size_t)l * DMODEL * 3*DMODEL;
        const __nv_bfloat16* wo_h   = g_w_hi + WO_OFF  + (size_t)l * DMODEL * DMODEL;
        const __nv_bfloat16* wo_l   = g_w_lo + WO_OFF  + (size_t)l * DMODEL * DMODEL;
        const __nv_bfloat16* w1_h   = g_w_hi + W1_OFF  + (size_t)l * DMODEL * DFF;
        const __nv_bfloat16* w1_l   = g_w_lo + W1_OFF  + (size_t)l * DMODEL * DFF;
        const __nv_bfloat16* w2_h   = g_w_hi + W2_OFF  + (size_t)l * DFF * DMODEL;
        const __nv_bfloat16* w2_l   = g_w_lo + W2_OFF  + (size_t)l * DFF * DMODEL;
        const float* bq = bqkv + (size_t)l * 3*DMODEL;
        const float* bO = bo   + (size_t)l * DMODEL;
        const float* B1 = b1   + (size_t)l * DFF;
        const float* B2 = b2   + (size_t)l * DMODEL;

        // pre-norm attention
        ln_kernel<<<TOKENS, 256>>>(g_h, ln1w + l*DMODEL, ln1b + l*DMODEL,
                                   g_hn, g_hn_hi, g_hn_lo);
        gemm_bf16x3<3><<<dim3(3*DMODEL/128, TOKENS/128), 256, GEMM_SMEM>>>(
            g_hn_hi, g_hn_lo, wqkv_h, wqkv_l, bq, nullptr,
            nullptr, g_qkv_hi, g_qkv_lo, TOKENS, 3*DMODEL, DMODEL);
        flash_kernel<<<dim3(BATCH*NHEAD, SEQ/128), 256, FL_SMEM>>>(
            g_qkv_hi, g_qkv_lo, g_o_hi, g_o_lo);
        gemm_bf16x3<1><<<dim3(DMODEL/128, TOKENS/128), 256, GEMM_SMEM>>>(
            g_o_hi, g_o_lo, wo_h, wo_l, bO, g_h,
            g_h, nullptr, nullptr, TOKENS, DMODEL, DMODEL);

        // pre-norm FFN
        ln_kernel<<<TOKENS, 256>>>(g_h, ln2w + l*DMODEL, ln2b + l*DMODEL,
                                   g_hn, g_hn_hi, g_hn_lo);
        gemm_bf16x3<2><<<dim3(DFF/128, TOKENS/128), 256, GEMM_SMEM>>>(
            g_hn_hi, g_hn_lo, w1_h, w1_l, B1, nullptr,
            nullptr, g_ff_hi, g_ff_lo, TOKENS, DFF, DMODEL);
        gemm_bf16x3<1><<<dim3(DMODEL/128, TOKENS/128), 256, GEMM_SMEM>>>(
            g_ff_hi, g_ff_lo, w2_h, w2_l, B2, g_h,
            g_h, nullptr, nullptr, TOKENS, DMODEL, DFF);
    }

    // final LN + projection
    ln_kernel<<<TOKENS, 256>>>(g_h, lnfw, lnfb, g_hn, g_hn_hi, g_hn_lo);
    pred_kernel<<<TOKENS, 256>>>(g_hn, Wp, bp, out);
    (void)in_sizes; (void)n_in; (void)out_size;
}

// round 5
// speedup vs baseline: 3.1457x; 1.0378x over previous
#include <cuda_runtime.h>
#include <cuda_bf16.h>
#include <math.h>
#include <stdint.h>

// ---------------- problem constants ----------------
#define LAYERS 6
#define BATCH  2
#define SEQ    1024
#define DMODEL 1024
#define NHEAD  16
#define HDIM   64
#define DFF    4096
#define WIN    5
#define TOKENS (BATCH*SEQ)          // 2048
#define EPS    1e-5f

// weight scratch layout (elements)
#define QKV_ELEMS  (LAYERS*DMODEL*3*DMODEL)
#define WO_ELEMS   (LAYERS*DMODEL*DMODEL)
#define W1_ELEMS   (LAYERS*DMODEL*DFF)
#define W2_ELEMS   (LAYERS*DFF*DMODEL)
#define QKV_OFF 0
#define WO_OFF  (QKV_ELEMS)
#define W1_OFF  (WO_OFF + WO_ELEMS)
#define W2_OFF  (W1_OFF + W1_ELEMS)
#define WTOTAL  (W2_OFF + W2_ELEMS)

// ---------------- device scratch (no allocation allowed) ----------------
__device__ float d_h   [TOKENS*DMODEL];
__device__ float d_hn  [TOKENS*DMODEL];
__device__ __nv_bfloat16 d_hn_hi[TOKENS*DMODEL];
__device__ __nv_bfloat16 d_hn_lo[TOKENS*DMODEL];
__device__ __nv_bfloat16 d_qkv_hi[TOKENS*3*DMODEL];
__device__ __nv_bfloat16 d_qkv_lo[TOKENS*3*DMODEL];
__device__ __nv_bfloat16 d_o_hi[TOKENS*DMODEL];
__device__ __nv_bfloat16 d_o_lo[TOKENS*DMODEL];
__device__ __nv_bfloat16 d_ff_hi[TOKENS*DFF];
__device__ __nv_bfloat16 d_ff_lo[TOKENS*DFF];
__device__ __nv_bfloat16 d_w_hi[WTOTAL];
__device__ __nv_bfloat16 d_w_lo[WTOTAL];

// ---------------- small helpers ----------------
__device__ __forceinline__ float warp_sum(float v){
    #pragma unroll
    for (int o = 16; o; o >>= 1) v += __shfl_xor_sync(0xffffffffu, v, o);
    return v;
}
__device__ __forceinline__ float gelu_exact(float x){
    return 0.5f * x * (1.0f + erff(x * 0.70710678118654752440f));
}
__device__ __forceinline__ uint32_t smem_u32(const void* p){
    uint32_t a;
    asm("{ .reg .u64 t; cvta.to.shared.u64 t, %1; cvt.u32.u64 %0, t; }" : "=r"(a) : "l"(p));
    return a;
}
__device__ __forceinline__ void split_bf16(float x, uint16_t& hi, uint16_t& lo){
    uint32_t u  = __float_as_uint(x);
    uint32_t hu = u & 0xFFFF0000u;
    hi = (uint16_t)(hu >> 16);
    float l = x - __uint_as_float(hu);
    lo = __bfloat16_as_ushort(__float2bfloat16(l));
}
__device__ __forceinline__ uint32_t pack_hi2(float x, float y){
    return (__float_as_uint(x) >> 16) | (__float_as_uint(y) & 0xFFFF0000u);
}
__device__ __forceinline__ uint32_t pack_lo2(float x, float y){
    float lx = x - __uint_as_float(__float_as_uint(x) & 0xFFFF0000u);
    float ly = y - __uint_as_float(__float_as_uint(y) & 0xFFFF0000u);
    __nv_bfloat162 t = __floats2bfloat162_rn(lx, ly);
    return *reinterpret_cast<uint32_t*>(&t);
}

// ---------------- mma.sync / ldmatrix / cp.async wrappers ----------------
__device__ __forceinline__ void mma_bf16(float* d, const uint32_t* a, const uint32_t* b){
    asm volatile(
      "mma.sync.aligned.m16n8k16.row.col.f32.bf16.bf16.f32 "
      "{%0,%1,%2,%3}, {%4,%5,%6,%7}, {%8,%9}, {%0,%1,%2,%3};\n"
      : "+f"(d[0]), "+f"(d[1]), "+f"(d[2]), "+f"(d[3])
      : "r"(a[0]), "r"(a[1]), "r"(a[2]), "r"(a[3]), "r"(b[0]), "r"(b[1]));
}
__device__ __forceinline__ void ldsm_x4(uint32_t* r, uint32_t addr){
    asm volatile("ldmatrix.sync.aligned.m8n8.x4.shared.b16 {%0,%1,%2,%3}, [%4];"
      : "=r"(r[0]), "=r"(r[1]), "=r"(r[2]), "=r"(r[3]) : "r"(addr));
}
__device__ __forceinline__ void ldsm_x2(uint32_t* r, uint32_t addr){
    asm volatile("ldmatrix.sync.aligned.m8n8.x2.shared.b16 {%0,%1}, [%2];"
      : "=r"(r[0]), "=r"(r[1]) : "r"(addr));
}
__device__ __forceinline__ void ldsm_x2t(uint32_t* r, uint32_t addr){
    asm volatile("ldmatrix.sync.aligned.m8n8.x2.trans.shared.b16 {%0,%1}, [%2];"
      : "=r"(r[0]), "=r"(r[1]) : "r"(addr));
}
__device__ __forceinline__ void cp16(uint32_t s, const void* g){
    asm volatile("cp.async.cg.shared.global [%0], [%1], 16;\n" :: "r"(s), "l"(g));
}

// ---------------- GEMM smem layout ----------------
#define KC          32
#define A_STRIDE    80
#define B_STRIDE    272
#define A_LO_OFF    10240
#define B_OFF       20480
#define B_LO_OFF    8704
#define STAGE_BYTES 37888
#define GEMM_SMEM   (3*STAGE_BYTES)

__device__ __forceinline__ void issue_stage(
    const __nv_bfloat16* __restrict__ Ah, const __nv_bfloat16* __restrict__ Al,
    const __nv_bfloat16* __restrict__ Bh, const __nv_bfloat16* __restrict__ Bl,
    uint32_t sb0, int tid, int m0, int n0, int K, int N, int c)
{
    uint32_t sb = sb0 + (uint32_t)(c % 3) * STAGE_BYTES;
    int k0 = c * KC;
    #pragma unroll
    for (int i = 0; i < 2; i++){
        int idx = tid + i*256;
        int r = idx >> 2, cc = idx & 3;
        uint32_t sa = sb + r*A_STRIDE + cc*16;
        size_t g = (size_t)(m0 + r) * K + k0 + cc*8;
        cp16(sa,            Ah + g);
        cp16(sa + A_LO_OFF, Al + g);
    }
    #pragma unroll
    for (int i = 0; i < 2; i++){
        int idx = tid + i*256;
        int r = idx >> 4, cc = idx & 15;
        uint32_t sa = sb + B_OFF + r*B_STRIDE + cc*16;
        size_t g = (size_t)(k0 + r) * N + n0 + cc*8;
        cp16(sa,            Bh + g);
        cp16(sa + B_LO_OFF, Bl + g);
    }
    asm volatile("cp.async.commit_group;");
}

// =====================================================================
// bf16x3 emulated-fp32 GEMM:  C[M,N] = epi(A @ B + bias)
// Single __syncthreads per chunk (wait -> sync -> issue -> compute),
// 3-sweep MMA ordering (no RAW chains on accumulators).
// EPI: 0 = bias (f32)  1 = bias+residual (f32)
//      2 = bias+GELU -> split bf16 hi/lo   3 = bias -> split bf16 hi/lo
// =====================================================================
template<int EPI>
__global__ __launch_bounds__(256)
void gemm_bf16x3(const __nv_bfloat16* __restrict__ Ah, const __nv_bfloat16* __restrict__ Al,
                 const __nv_bfloat16* __restrict__ Bh, const __nv_bfloat16* __restrict__ Bl,
                 const float* __restrict__ bias, const float* __restrict__ res,
                 float* __restrict__ C,
                 __nv_bfloat16* __restrict__ Chi, __nv_bfloat16* __restrict__ Clo,
                 int M, int N, int K)
{
    extern __shared__ char smem[];
    const uint32_t sb0 = smem_u32(smem);
    const int tid  = threadIdx.x;
    const int lane = tid & 31, wid = tid >> 5;
    const int m0 = blockIdx.y * 128, n0 = blockIdx.x * 128;
    const int wm = (wid >> 2) * 64, wn = (wid & 3) * 32;

    float acc[4][4][4];
    #pragma unroll
    for (int a = 0; a < 4; a++)
        #pragma unroll
        for (int b = 0; b < 4; b++)
            #pragma unroll
            for (int cc = 0; cc < 4; cc++) acc[a][b][cc] = 0.f;

    const int nch = K / KC;
    issue_stage(Ah, Al, Bh, Bl, sb0, tid, m0, n0, K, N, 0);
    issue_stage(Ah, Al, Bh, Bl, sb0, tid, m0, n0, K, N, 1);

    const uint32_t a_lrow = wm + (lane & 15);
    const uint32_t a_lcol = (lane >> 4) * 8;
    const uint32_t b_lrow = (lane & 15);

    for (int c = 0; c < nch; c++){
        asm volatile("cp.async.wait_group %0;" :: "n"(1));
        __syncthreads();
        if (c + 2 < nch) issue_stage(Ah, Al, Bh, Bl, sb0, tid, m0, n0, K, N, c + 2);
        else asm volatile("cp.async.commit_group;");

        uint32_t sb = sb0 + (uint32_t)(c % 3) * STAGE_BYTES;
        #pragma unroll
        for (int ks = 0; ks < 2; ks++){
            uint32_t ah[4][4], al[4][4], bh[4][2], bl[4][2];
            #pragma unroll
            for (int mt = 0; mt < 4; mt++){
                uint32_t ad = sb + (a_lrow + mt*16)*A_STRIDE + (ks*16 + a_lcol)*2;
                ldsm_x4(ah[mt], ad);
                ldsm_x4(al[mt], ad + A_LO_OFF);
            }
            #pragma unroll
            for (int nt = 0; nt < 4; nt++){
                uint32_t bd = sb + B_OFF + (ks*16 + b_lrow)*B_STRIDE + (wn + nt*8)*2;
                ldsm_x2t(bh[nt], bd);
                ldsm_x2t(bl[nt], bd + B_LO_OFF);
            }
            // 3 sweeps: adjacent MMAs always hit different accumulators
            #pragma unroll
            for (int mt = 0; mt < 4; mt++)
                #pragma unroll
                for (int nt = 0; nt < 4; nt++)
                    mma_bf16(acc[mt][nt], ah[mt], bh[nt]);
            #pragma unroll
            for (int mt = 0; mt < 4; mt++)
                #pragma unroll
                for (int nt = 0; nt < 4; nt++)
                    mma_bf16(acc[mt][nt], ah[mt], bl[nt]);
            #pragma unroll
            for (int mt = 0; mt < 4; mt++)
                #pragma unroll
                for (int nt = 0; nt < 4; nt++)
                    mma_bf16(acc[mt][nt], al[mt], bh[nt]);
        }
    }

    // ---- epilogue ----
    const int g  = lane >> 2;
    const int tq = (lane & 3) * 2;
    #pragma unroll
    for (int mt = 0; mt < 4; mt++){
        #pragma unroll
        for (int half = 0; half < 2; half++){
            int m = m0 + wm + mt*16 + g + half*8;
            #pragma unroll
            for (int nt = 0; nt < 4; nt++){
                int n = n0 + wn + nt*8 + tq;
                float v0 = acc[mt][nt][half*2+0] + bias[n];
                float v1 = acc[mt][nt][half*2+1] + bias[n+1];
                size_t gi = (size_t)m * N + n;
                if (EPI == 1){ v0 += res[gi]; v1 += res[gi+1]; }
                if (EPI >= 2){
                    if (EPI == 2){ v0 = gelu_exact(v0); v1 = gelu_exact(v1); }
                    *(uint32_t*)&Chi[gi] = pack_hi2(v0, v1);
                    *(uint32_t*)&Clo[gi] = pack_lo2(v0, v1);
                } else {
                    float2 o; o.x = v0; o.y = v1;
                    *(float2*)&C[gi] = o;
                }
            }
        }
    }
}

// =====================================================================
// Flash attention, bf16x3, causal.  Bq=128 (8 warps x 16 rows), Bc=64.
// =====================================================================
#define FL_SMEM 110592

__global__ __launch_bounds__(256)
void flash_kernel(const __nv_bfloat16* __restrict__ qkv_hi,
                  const __nv_bfloat16* __restrict__ qkv_lo,
                  __nv_bfloat16* __restrict__ o_hi,
                  __nv_bfloat16* __restrict__ o_lo)
{
    extern __shared__ char fsm[];
    const uint32_t sb = smem_u32(fsm);
    const int tid = threadIdx.x, lane = tid & 31, w = tid >> 5;
    const int bh = blockIdx.x;
    const int it = 7 - blockIdx.y;           // heavy q-tiles first
    const int b = bh >> 4, h = bh & 15;
    const int nk = 2*(it+1);
    const size_t rs = 3*DMODEL;

    {
        const size_t tok0 = (size_t)(b*SEQ + it*128);
        #pragma unroll
        for (int i = 0; i < 4; i++){
            int idx = tid + i*256;
            int r = idx >> 3, c = idx & 7;
            size_t g = (tok0 + r)*rs + h*64 + c*8;
            uint32_t sa = sb + r*144 + c*16;
            cp16(sa,         qkv_hi + g);
            cp16(sa + 18432, qkv_lo + g);
        }
        asm volatile("cp.async.commit_group;");
    }
    #define ISSUE_KV(jt_) do {                                               \
        uint32_t st_ = sb + 36864u + (uint32_t)((jt_)&1)*36864u;             \
        const size_t tok0_ = (size_t)(b*SEQ + (jt_)*64);                     \
        _Pragma("unroll")                                                    \
        for (int i_ = 0; i_ < 2; i_++){                                      \
            int idx_ = tid + i_*256;                                         \
            int r_ = idx_ >> 3, c_ = idx_ & 7;                               \
            size_t gk_ = (tok0_ + r_)*rs + DMODEL   + h*64 + c_*8;           \
            size_t gv_ = (tok0_ + r_)*rs + 2*DMODEL + h*64 + c_*8;           \
            uint32_t sa_ = st_ + r_*144 + c_*16;                             \
            cp16(sa_,         qkv_hi + gk_);                                 \
            cp16(sa_ + 9216,  qkv_lo + gk_);                                 \
            cp16(sa_ + 18432, qkv_hi + gv_);                                 \
            cp16(sa_ + 27648, qkv_lo + gv_);                                 \
        }                                                                    \
        asm volatile("cp.async.commit_group;");                              \
    } while(0)

    ISSUE_KV(0);
    asm volatile("cp.async.wait_group 1;");   // Q ready
    __syncthreads();

    uint32_t qh[4][4], ql[4][4];
    {
        uint32_t rbase = sb + (w*16 + (lane & 15))*144 + ((lane >> 4)*8)*2;
        #pragma unroll
        for (int ks = 0; ks < 4; ks++){
            ldsm_x4(qh[ks], rbase + ks*32);
            ldsm_x4(ql[ks], rbase + ks*32 + 18432);
        }
    }

    float O[8][4];
    #pragma unroll
    for (int nt = 0; nt < 8; nt++)
        #pragma unroll
        for (int c = 0; c < 4; c++) O[nt][c] = 0.f;
    float m0 = -INFINITY, m1 = -INFINITY, l0 = 0.f, l1 = 0.f;
    const int r0g = it*128 + w*16 + (lane >> 2);

    for (int jt = 0; jt < nk; jt++){
        if (jt + 1 < nk){ ISSUE_KV(jt+1); asm volatile("cp.async.wait_group 1;"); }
        else            { asm volatile("cp.async.wait_group 0;"); }
        __syncthreads();
        const uint32_t st = sb + 36864u + (uint32_t)(jt&1)*36864u;

        float S[8][4];
        #pragma unroll
        for (int nt = 0; nt < 8; nt++)
            #pragma unroll
            for (int c = 0; c < 4; c++) S[nt][c] = 0.f;

        const uint32_t kb = st + (lane & 7)*144 + (((lane >> 3) & 1)*8)*2;
        #pragma unroll
        for (int nt = 0; nt < 8; nt++){
            #pragma unroll
            for (int ks = 0; ks < 4; ks++){
                uint32_t a = kb + nt*8*144 + ks*32;
                uint32_t kh[2], kl[2];
                ldsm_x2(kh, a);
                ldsm_x2(kl, a + 9216);
                mma_bf16(S[nt], qh[ks], kh);
                mma_bf16(S[nt], qh[ks], kl);
                mma_bf16(S[nt], ql[ks], kh);
            }
        }

        const bool diag = (jt >= 2*it);
        float mx0 = -INFINITY, mx1 = -INFINITY;
        #pragma unroll
        for (int nt = 0; nt < 8; nt++){
            int colb = jt*64 + nt*8 + (lane & 3)*2;
            #pragma unroll
            for (int q = 0; q < 2; q++){
                float v0 = S[nt][q]   * 0.125f;
                float v1 = S[nt][2+q] * 0.125f;
                if (diag){
                    if (colb + q > r0g)     v0 = -INFINITY;
                    if (colb + q > r0g + 8) v1 = -INFINITY;
                }
                S[nt][q] = v0; S[nt][2+q] = v1;
                mx0 = fmaxf(mx0, v0); mx1 = fmaxf(mx1, v1);
            }
        }
        mx0 = fmaxf(mx0, __shfl_xor_sync(0xffffffffu, mx0, 1));
        mx0 = fmaxf(mx0, __shfl_xor_sync(0xffffffffu, mx0, 2));
        mx1 = fmaxf(mx1, __shfl_xor_sync(0xffffffffu, mx1, 1));
        mx1 = fmaxf(mx1, __shfl_xor_sync(0xffffffffu, mx1, 2));
        float mn0 = fmaxf(m0, mx0), mn1 = fmaxf(m1, mx1);
        float f0 = __expf(m0 - mn0), f1 = __expf(m1 - mn1);
        m0 = mn0; m1 = mn1;
        float ls0 = 0.f, ls1 = 0.f;
        #pragma unroll
        for (int nt = 0; nt < 8; nt++){
            #pragma unroll
            for (int q = 0; q < 2; q++){
                float e0 = __expf(S[nt][q]   - m0);
                float e1 = __expf(S[nt][2+q] - m1);
                S[nt][q] = e0; S[nt][2+q] = e1;
                ls0 += e0; ls1 += e1;
            }
        }
        l0 = l0*f0 + ls0;
        l1 = l1*f1 + ls1;
        #pragma unroll
        for (int nt = 0; nt < 8; nt++){
            O[nt][0] *= f0; O[nt][1] *= f0;
            O[nt][2] *= f1; O[nt][3] *= f1;
        }

        #pragma unroll
        for (int ks = 0; ks < 4; ks++){
            uint32_t ph[4], pl[4];
            ph[0] = pack_hi2(S[2*ks][0],   S[2*ks][1]);
            ph[1] = pack_hi2(S[2*ks][2],   S[2*ks][3]);
            ph[2] = pack_hi2(S[2*ks+1][0], S[2*ks+1][1]);
            ph[3] = pack_hi2(S[2*ks+1][2], S[2*ks+1][3]);
            pl[0] = pack_lo2(S[2*ks][0],   S[2*ks][1]);
            pl[1] = pack_lo2(S[2*ks][2],   S[2*ks][3]);
            pl[2] = pack_lo2(S[2*ks+1][0], S[2*ks+1][1]);
            pl[3] = pack_lo2(S[2*ks+1][2], S[2*ks+1][3]);
            uint32_t vb = st + 18432u + (ks*16 + (lane & 15))*144;
            #pragma unroll
            for (int nt = 0; nt < 8; nt++){
                uint32_t vh[2], vl[2];
                ldsm_x2t(vh, vb + nt*16);
                ldsm_x2t(vl, vb + nt*16 + 9216);
                mma_bf16(O[nt], ph, vh);
                mma_bf16(O[nt], ph, vl);
                mma_bf16(O[nt], pl, vh);
            }
        }
        __syncthreads();
    }

    l0 += __shfl_xor_sync(0xffffffffu, l0, 1);
    l0 += __shfl_xor_sync(0xffffffffu, l0, 2);
    l1 += __shfl_xor_sync(0xffffffffu, l1, 1);
    l1 += __shfl_xor_sync(0xffffffffu, l1, 2);
    float inv0 = 1.0f / l0, inv1 = 1.0f / l1;
    const size_t tok0 = (size_t)(b*SEQ + it*128 + w*16 + (lane >> 2));
    const int colb = h*64 + (lane & 3)*2;
    #pragma unroll
    for (int nt = 0; nt < 8; nt++){
        #pragma unroll
        for (int rh = 0; rh < 2; rh++){
            float inv = rh ? inv1 : inv0;
            float v0 = O[nt][rh*2+0] * inv;
            float v1 = O[nt][rh*2+1] * inv;
            size_t gi = (tok0 + rh*8)*DMODEL + colb + nt*8;
            *(uint32_t*)&o_hi[gi] = pack_hi2(v0, v1);
            *(uint32_t*)&o_lo[gi] = pack_lo2(v0, v1);
        }
    }
}

// ---------------- weight split: fp32 -> bf16 hi/lo ----------------
__global__ void wsplit_kernel(const float4* __restrict__ in,
                              uint2* __restrict__ hi, uint2* __restrict__ lo, int n4){
    int i = blockIdx.x * blockDim.x + threadIdx.x;
    if (i >= n4) return;
    float4 v = in[i];
    uint2 H, L;
    H.x = pack_hi2(v.x, v.y); H.y = pack_hi2(v.z, v.w);
    L.x = pack_lo2(v.x, v.y); L.y = pack_lo2(v.z, v.w);
    hi[i] = H; lo[i] = L;
}

// ---------------- copy x -> h ----------------
__global__ void copy_kernel(const float* __restrict__ in, float* __restrict__ out){
    int idx = blockIdx.x * blockDim.x + threadIdx.x;
    float4 v = ((const float4*)in)[idx];
    ((float4*)out)[idx] = v;
}

// ---------------- LayerNorm (bf16 hi/lo out; fp32 out optional) ----------------
template<bool WF32>
__global__ void ln_kernel(const float* __restrict__ in,
                          const float* __restrict__ w,
                          const float* __restrict__ b,
                          float* __restrict__ out,
                          __nv_bfloat16* __restrict__ out_hi,
                          __nv_bfloat16* __restrict__ out_lo){
    int row = blockIdx.x;
    int t   = threadIdx.x;
    const float* x = in + (size_t)row * DMODEL;
    float4 v = *(const float4*)&x[t*4];
    float s  = v.x + v.y + v.z + v.w;
    float sq = v.x*v.x + v.y*v.y + v.z*v.z + v.w*v.w;
    s  = warp_sum(s);
    sq = warp_sum(sq);
    __shared__ float sh1[8], sh2[8];
    int warp = t >> 5, lane = t & 31;
    if (lane == 0){ sh1[warp] = s; sh2[warp] = sq; }
    __syncthreads();
    float tot = 0.f, tot2 = 0.f;
    #pragma unroll
    for (int i = 0; i < 8; i++){ tot += sh1[i]; tot2 += sh2[i]; }
    float mu   = tot  * (1.0f/DMODEL);
    float var  = tot2 * (1.0f/DMODEL) - mu*mu;
    float rstd = rsqrtf(var + EPS);
    float4 wv = *(const float4*)&w[t*4];
    float4 bv = *(const float4*)&b[t*4];
    float4 ov;
    ov.x = (v.x - mu)*rstd*wv.x + bv.x;
    ov.y = (v.y - mu)*rstd*wv.y + bv.y;
    ov.z = (v.z - mu)*rstd*wv.z + bv.z;
    ov.w = (v.w - mu)*rstd*wv.w + bv.w;
    size_t base = (size_t)row*DMODEL + t*4;
    if (WF32) *(float4*)&out[base] = ov;
    uint2 H, L;
    H.x = pack_hi2(ov.x, ov.y); H.y = pack_hi2(ov.z, ov.w);
    L.x = pack_lo2(ov.x, ov.y); L.y = pack_lo2(ov.z, ov.w);
    *(uint2*)&out_hi[base] = H;
    *(uint2*)&out_lo[base] = L;
}

// ---------------- final projection ----------------
__global__ __launch_bounds__(256)
void pred_kernel(const float* __restrict__ hn, const float* __restrict__ Wp,
                 const float* __restrict__ bp, float* __restrict__ out){
    int row = blockIdx.x;
    int t = threadIdx.x;
    float local[WIN] = {0,0,0,0,0};
    const float* x = hn + (size_t)row * DMODEL;
    for (int k = t; k < DMODEL; k += 256){
        float xv = x[k];
        const float* wr = Wp + (size_t)k * WIN;
        #pragma unroll
        for (int w = 0; w < WIN; w++) local[w] = fmaf(xv, wr[w], local[w]);
    }
    __shared__ float red[WIN][256];
    #pragma unroll
    for (int w = 0; w < WIN; w++) red[w][t] = local[w];
    __syncthreads();
    for (int s = 128; s > 0; s >>= 1){
        if (t < s){
            #pragma unroll
            for (int w = 0; w < WIN; w++) red[w][t] += red[w][t + s];
        }
        __syncthreads();
    }
    if (t < WIN) out[(size_t)row * WIN + t] = red[t][0] + bp[t];
}

// ---------------- host orchestration ----------------
extern "C" void kernel_launch(void* const* d_in, const int* in_sizes, int n_in,
                              void* d_out, int out_size){
    const float* x     = (const float*)d_in[0];
    const float* Wqkv  = (const float*)d_in[1];
    const float* bqkv  = (const float*)d_in[2];
    const float* Wo    = (const float*)d_in[3];
    const float* bo    = (const float*)d_in[4];
    const float* ln1w  = (const float*)d_in[5];
    const float* ln1b  = (const float*)d_in[6];
    const float* W1    = (const float*)d_in[7];
    const float* b1    = (const float*)d_in[8];
    const float* W2    = (const float*)d_in[9];
    const float* b2    = (const float*)d_in[10];
    const float* ln2w  = (const float*)d_in[11];
    const float* ln2b  = (const float*)d_in[12];
    const float* lnfw  = (const float*)d_in[13];
    const float* lnfb  = (const float*)d_in[14];
    const float* Wp    = (const float*)d_in[15];
    const float* bp    = (const float*)d_in[16];
    float* out = (float*)d_out;

    float *g_h, *g_hn;
    __nv_bfloat16 *g_hn_hi, *g_hn_lo, *g_qkv_hi, *g_qkv_lo,
                  *g_o_hi, *g_o_lo, *g_ff_hi, *g_ff_lo, *g_w_hi, *g_w_lo;
    cudaGetSymbolAddress((void**)&g_h,      d_h);
    cudaGetSymbolAddress((void**)&g_hn,     d_hn);
    cudaGetSymbolAddress((void**)&g_hn_hi,  d_hn_hi);
    cudaGetSymbolAddress((void**)&g_hn_lo,  d_hn_lo);
    cudaGetSymbolAddress((void**)&g_qkv_hi, d_qkv_hi);
    cudaGetSymbolAddress((void**)&g_qkv_lo, d_qkv_lo);
    cudaGetSymbolAddress((void**)&g_o_hi,   d_o_hi);
    cudaGetSymbolAddress((void**)&g_o_lo,   d_o_lo);
    cudaGetSymbolAddress((void**)&g_ff_hi,  d_ff_hi);
    cudaGetSymbolAddress((void**)&g_ff_lo,  d_ff_lo);
    cudaGetSymbolAddress((void**)&g_w_hi,   d_w_hi);
    cudaGetSymbolAddress((void**)&g_w_lo,   d_w_lo);

    cudaFuncSetAttribute(gemm_bf16x3<0>, cudaFuncAttributeMaxDynamicSharedMemorySize, GEMM_SMEM);
    cudaFuncSetAttribute(gemm_bf16x3<1>, cudaFuncAttributeMaxDynamicSharedMemorySize, GEMM_SMEM);
    cudaFuncSetAttribute(gemm_bf16x3<2>, cudaFuncAttributeMaxDynamicSharedMemorySize, GEMM_SMEM);
    cudaFuncSetAttribute(gemm_bf16x3<3>, cudaFuncAttributeMaxDynamicSharedMemorySize, GEMM_SMEM);
    cudaFuncSetAttribute(flash_kernel,   cudaFuncAttributeMaxDynamicSharedMemorySize, FL_SMEM);

    wsplit_kernel<<<QKV_ELEMS/4/256, 256>>>((const float4*)Wqkv,
        (uint2*)(g_w_hi + QKV_OFF), (uint2*)(g_w_lo + QKV_OFF), QKV_ELEMS/4);
    wsplit_kernel<<<WO_ELEMS/4/256, 256>>>((const float4*)Wo,
        (uint2*)(g_w_hi + WO_OFF),  (uint2*)(g_w_lo + WO_OFF),  WO_ELEMS/4);
    wsplit_kernel<<<W1_ELEMS/4/256, 256>>>((const float4*)W1,
        (uint2*)(g_w_hi + W1_OFF),  (uint2*)(g_w_lo + W1_OFF),  W1_ELEMS/4);
    wsplit_kernel<<<W2_ELEMS/4/256, 256>>>((const float4*)W2,
        (uint2*)(g_w_hi + W2_OFF),  (uint2*)(g_w_lo + W2_OFF),  W2_ELEMS/4);

    copy_kernel<<<TOKENS*DMODEL/4/256, 256>>>(x, g_h);

    for (int l = 0; l < LAYERS; l++){
        const __nv_bfloat16* wqkv_h = g_w_hi + QKV_OFF + (size_t)l * DMODEL * 3*DMODEL;
        const __nv_bfloat16* wqkv_l = g_w_lo + QKV_OFF + (size_t)l * DMODEL * 3*DMODEL;
        const __nv_bfloat16* wo_h   = g_w_hi + WO_OFF  + (size_t)l * DMODEL * DMODEL;
        const __nv_bfloat16* wo_l   = g_w_lo + WO_OFF  + (size_t)l * DMODEL * DMODEL;
        const __nv_bfloat16* w1_h   = g_w_hi + W1_OFF  + (size_t)l * DMODEL * DFF;
        const __nv_bfloat16* w1_l   = g_w_lo + W1_OFF  + (size_t)l * DMODEL * DFF;
        const __nv_bfloat16* w2_h   = g_w_hi + W2_OFF  + (size_t)l * DFF * DMODEL;
        const __nv_bfloat16* w2_l   = g_w_lo + W2_OFF  + (size_t)l * DFF * DMODEL;
        const float* bq = bqkv + (size_t)l * 3*DMODEL;
        const float* bO = bo   + (size_t)l * DMODEL;
        const float* B1 = b1   + (size_t)l * DFF;
        const float* B2 = b2   + (size_t)l * DMODEL;

        // pre-norm attention
        ln_kernel<false><<<TOKENS, 256>>>(g_h, ln1w + l*DMODEL, ln1b + l*DMODEL,
                                          nullptr, g_hn_hi, g_hn_lo);
        gemm_bf16x3<3><<<dim3(3*DMODEL/128, TOKENS/128), 256, GEMM_SMEM>>>(
            g_hn_hi, g_hn_lo, wqkv_h, wqkv_l, bq, nullptr,
            nullptr, g_qkv_hi, g_qkv_lo, TOKENS, 3*DMODEL, DMODEL);
        flash_kernel<<<dim3(BATCH*NHEAD, SEQ/128), 256, FL_SMEM>>>(
            g_qkv_hi, g_qkv_lo, g_o_hi, g_o_lo);
        gemm_bf16x3<1><<<dim3(DMODEL/128, TOKENS/128), 256, GEMM_SMEM>>>(
            g_o_hi, g_o_lo, wo_h, wo_l, bO, g_h,
            g_h, nullptr, nullptr, TOKENS, DMODEL, DMODEL);

        // pre-norm FFN
        ln_kernel<false><<<TOKENS, 256>>>(g_h, ln2w + l*DMODEL, ln2b + l*DMODEL,
                                          nullptr, g_hn_hi, g_hn_lo);
        gemm_bf16x3<2><<<dim3(DFF/128, TOKENS/128), 256, GEMM_SMEM>>>(
            g_hn_hi, g_hn_lo, w1_h, w1_l, B1, nullptr,
            nullptr, g_ff_hi, g_ff_lo, TOKENS, DFF, DMODEL);
        gemm_bf16x3<1><<<dim3(DMODEL/128, TOKENS/128), 256, GEMM_SMEM>>>(
            g_ff_hi, g_ff_lo, w2_h, w2_l, B2, g_h,
            g_h, nullptr, nullptr, TOKENS, DMODEL, DFF);
    }

    // final LN + projection
    ln_kernel<true><<<TOKENS, 256>>>(g_h, lnfw, lnfb, g_hn, g_hn_hi, g_hn_lo);
    pred_kernel<<<TOKENS, 256>>>(g_hn, Wp, bp, out);
    (void)in_sizes; (void)n_in; (void)out_size;
}